// round 4
// baseline (speedup 1.0000x reference)
#include <cuda_runtime.h>
#include <math.h>
#include <stdint.h>

#define BB 4
#define SS 1024
#define DD 1024
#define TT (BB*SS)           // 4096 tokens
#define HH 16
#define KVHH 4
#define HDD 64
#define EE 8
#define FFF 2816
#define CCOMP 256
#define NSLOT (TT*2)

// GEMM pipeline geometry
#define ASTRIDE 36           // 32 + 4 pad  (bank = 4*mq+kq, conflict-free)
#define BSTRIDE 132          // 128 + 4 pad (bank = 4*kq+mq, conflict-free)
#define ASTG (128*ASTRIDE)   // floats per A stage
#define BSTG (32*BSTRIDE)    // floats per B stage
#define NSTAGE 3
#define GSMEM ((NSTAGE*(ASTG+BSTG))*4)   // 105984 bytes

// ---------------- scratch (static device globals) -----------------------------
__device__ float g_X[TT*DD];
__device__ float g_Q[TT*DD];
__device__ float g_K[TT*KVHH*HDD];
__device__ float g_V[TT*KVHH*HDD];
__device__ float g_attn[TT*DD];
__device__ float g_attnout[TT*DD];
__device__ float g_h2[TT*DD];
__device__ float g_act[NSLOT*FFF];
__device__ float g_h3[NSLOT*FFF];
__device__ float g_part[NSLOT*DD];
__device__ int   g_tok[NSLOT];
__device__ float g_slotw[NSLOT];
__device__ int   g_tokslot[TT*2];
__device__ int   g_te[TT*2];
__device__ float g_tw[TT*2];
__device__ int   g_cnt[EE];
__device__ int   g_off[EE+1];
__device__ int   g_cur[EE];

// ---------------- helpers -----------------------------------------------------
__device__ __forceinline__ uint32_t f2tf(float f) {
  uint32_t u;
  asm("cvt.rna.tf32.f32 %0, %1;" : "=r"(u) : "f"(f));
  return u;
}
__device__ __forceinline__ void mma_tf32(float c[4],
    uint32_t a0, uint32_t a1, uint32_t a2, uint32_t a3,
    uint32_t b0, uint32_t b1) {
  asm volatile(
    "mma.sync.aligned.m16n8k8.row.col.f32.tf32.tf32.f32 "
    "{%0,%1,%2,%3},{%4,%5,%6,%7},{%8,%9},{%0,%1,%2,%3};"
    : "+f"(c[0]), "+f"(c[1]), "+f"(c[2]), "+f"(c[3])
    : "r"(a0), "r"(a1), "r"(a2), "r"(a3), "r"(b0), "r"(b1));
}
__device__ __forceinline__ uint32_t smem_u32(const void* p) {
  return (uint32_t)__cvta_generic_to_shared(p);
}
__device__ __forceinline__ void cpa16(uint32_t s, const void* g) {
  asm volatile("cp.async.cg.shared.global [%0], [%1], 16;" :: "r"(s), "l"(g));
}

// ---------------- unified TF32 GEMM, cp.async 3-stage pipeline ----------------
// Block 128x128, 256 thr = 8 warps (2 warpM x 4 warpN), warp tile 64x32, Kc=32.
// MODE 0: C = A@B (+bias)   MODE 1: mix (A|A2 over K=2048; C=mixed, C2=h)
// MODE 2: MoE gathered rows MODE 3: MoE down (slot rows, slotw scale)
// MODE 4: fused QKV (B/B2/B3 -> C/C2/C3 selected by colBase)
template<int MODE>
__global__ __launch_bounds__(256) void gemm_tf32(
    const float* __restrict__ A, const float* __restrict__ A2,
    const float* __restrict__ B, const float* __restrict__ B2,
    const float* __restrict__ B3, const float* __restrict__ bias,
    const float* __restrict__ hidden, float* __restrict__ C,
    float* __restrict__ C2, float* __restrict__ C3, int K, int N) {
  extern __shared__ float sm[];
  float* As = sm;                       // [NSTAGE][128][ASTRIDE]
  float* Bs = sm + NSTAGE * ASTG;       // [NSTAGE][32][BSTRIDE]

  int base = 0, cnt = 0;
  if (MODE == 2 || MODE == 3) {
    int e = blockIdx.z;
    base = g_off[e];
    cnt = g_off[e+1] - base;
    if ((int)(blockIdx.y * 128) >= cnt) return;
    B += (size_t)e * K * N;
  }
  int rowBase = blockIdx.y * 128;
  int colBase = blockIdx.x * 128;
  int tid = threadIdx.x;
  int lane = tid & 31;
  int warp = tid >> 5;
  int warpM = warp & 1;
  int warpN = warp >> 1;

  // MODE 4 column-range select
  const float* Bsel = B;
  float* Csel = C;
  int bN = N, cOff = 0;
  if (MODE == 4) {
    if (colBase < DD)            { Bsel = B;  Csel = C;  bN = DD;  cOff = 0; }
    else if (colBase < DD + 256) { Bsel = B2; Csel = C2; bN = 256; cOff = DD; }
    else                         { Bsel = B3; Csel = C3; bN = 256; cOff = DD + 256; }
  }

  // ---- A fill: thread covers one row (tid>>1), 4x16B segments -----------
  int ar = tid >> 1;                    // 0..127
  int asg = (tid & 1) * 4;              // seg start (each seg = 4 floats)
  const float* arow0 = nullptr;
  const float* arow1 = nullptr;
  if (MODE == 0 || MODE == 4) {
    arow0 = A + (size_t)(rowBase + ar) * K;
  } else if (MODE == 1) {
    arow0 = A  + (size_t)(rowBase + ar) * DD;
    arow1 = A2 + (size_t)(rowBase + ar) * DD;
  } else if (MODE == 2) {
    int rr = rowBase + ar; if (rr > cnt - 1) rr = cnt - 1;
    arow0 = A + (size_t)g_tok[base + rr] * K;
  } else {
    int rr = rowBase + ar; if (rr > cnt - 1) rr = cnt - 1;
    arow0 = A + (size_t)(base + rr) * K;
  }
  uint32_t aSm = smem_u32(As) + (uint32_t)((ar * ASTRIDE + asg * 4) * 4);

  // ---- B fill: thread covers row (tid>>3), 4 segments 128B apart --------
  int br = tid >> 3;                    // 0..31
  int bsg = tid & 7;
  const float* brow = Bsel + (size_t)br * bN + (colBase - cOff) + bsg * 4;
  uint32_t bSm = smem_u32(Bs) + (uint32_t)((br * BSTRIDE + bsg * 4) * 4);

  auto issue = [&](int stage, int k0) {
    const float* ap = arow0;
    int kk0 = k0;
    if (MODE == 1 && k0 >= DD) { ap = arow1; kk0 = k0 - DD; }
    uint32_t sa = aSm + (uint32_t)(stage * ASTG * 4);
#pragma unroll
    for (int j = 0; j < 4; j++)
      cpa16(sa + j * 16, ap + kk0 + (asg + j) * 4);
    uint32_t sb = bSm + (uint32_t)(stage * BSTG * 4);
#pragma unroll
    for (int j = 0; j < 4; j++)
      cpa16(sb + j * 128, brow + (size_t)k0 * bN + j * 32);
  };

  float acc[4][4][4] = {};
  int kq = lane & 3;
  int mq = lane >> 2;
  int nch = K / 32;

  issue(0, 0);
  asm volatile("cp.async.commit_group;");
  issue(1, 32);
  asm volatile("cp.async.commit_group;");

  for (int i = 0; i < nch; i++) {
    asm volatile("cp.async.wait_group 1;");
    __syncthreads();
    int nk = i + 2;
    if (nk < nch) issue(nk % NSTAGE, nk * 32);
    asm volatile("cp.async.commit_group;");

    const float* Ast = As + (i % NSTAGE) * ASTG;
    const float* Bst = Bs + (i % NSTAGE) * BSTG;
#pragma unroll
    for (int kc = 0; kc < 4; kc++) {
      int kb = kc * 8;
      uint32_t af[4][4];
#pragma unroll
      for (int mt = 0; mt < 4; mt++) {
        int mb = warpM * 64 + mt * 16 + mq;
        af[mt][0] = f2tf(Ast[(mb    ) * ASTRIDE + kb + kq    ]);
        af[mt][1] = f2tf(Ast[(mb + 8) * ASTRIDE + kb + kq    ]);
        af[mt][2] = f2tf(Ast[(mb    ) * ASTRIDE + kb + kq + 4]);
        af[mt][3] = f2tf(Ast[(mb + 8) * ASTRIDE + kb + kq + 4]);
      }
      uint32_t bf[4][2];
#pragma unroll
      for (int nt = 0; nt < 4; nt++) {
        int nb = warpN * 32 + nt * 8 + mq;
        bf[nt][0] = f2tf(Bst[(kb + kq    ) * BSTRIDE + nb]);
        bf[nt][1] = f2tf(Bst[(kb + kq + 4) * BSTRIDE + nb]);
      }
#pragma unroll
      for (int mt = 0; mt < 4; mt++)
#pragma unroll
        for (int nt = 0; nt < 4; nt++)
          mma_tf32(acc[mt][nt], af[mt][0], af[mt][1], af[mt][2], af[mt][3],
                   bf[nt][0], bf[nt][1]);
    }
  }

  // ---- epilogue ----
#pragma unroll
  for (int mt = 0; mt < 4; mt++) {
#pragma unroll
    for (int half = 0; half < 2; half++) {
      int r = rowBase + warpM * 64 + mt * 16 + mq + half * 8;
#pragma unroll
      for (int nt = 0; nt < 4; nt++) {
        int n = colBase + warpN * 32 + nt * 8 + 2 * kq;
        float v0 = acc[mt][nt][half * 2];
        float v1 = acc[mt][nt][half * 2 + 1];
        if (MODE == 0) {
          if (bias) { v0 += bias[n]; v1 += bias[n + 1]; }
          *(float2*)(C + (size_t)r * N + n) = make_float2(v0, v1);
        } else if (MODE == 1) {
          v0 += bias[n]; v1 += bias[n + 1];
          *(float2*)(C + (size_t)r * N + n) = make_float2(v0, v1);
          float h0 = hidden[(size_t)r * N + n];
          float h1 = hidden[(size_t)r * N + n + 1];
          *(float2*)(C2 + (size_t)r * N + n) = make_float2(h0 + v0, h1 + v1);
        } else if (MODE == 2) {
          if (r < cnt)
            *(float2*)(C + (size_t)(base + r) * N + n) = make_float2(v0, v1);
        } else if (MODE == 3) {
          if (r < cnt) {
            float w = g_slotw[base + r];
            *(float2*)(C + (size_t)(base + r) * N + n) = make_float2(w*v0, w*v1);
          }
        } else {  // MODE 4
          *(float2*)(Csel + (size_t)r * bN + (n - cOff)) = make_float2(v0, v1);
        }
      }
    }
  }
}

// ---------------- rmsnorm ----------------------------------------------------
__global__ __launch_bounds__(256) void rmsnorm_kernel(
    const float* __restrict__ x, const float* __restrict__ w, float* __restrict__ out) {
  int row = blockIdx.x;
  const float* xr = x + (size_t)row * DD;
  float ss = 0.f;
  for (int i = threadIdx.x; i < DD; i += 256) { float v = xr[i]; ss += v * v; }
  __shared__ float red[8];
#pragma unroll
  for (int o = 16; o; o >>= 1) ss += __shfl_xor_sync(0xffffffffu, ss, o);
  if ((threadIdx.x & 31) == 0) red[threadIdx.x >> 5] = ss;
  __syncthreads();
  if (threadIdx.x < 8) {
    float v = red[threadIdx.x];
#pragma unroll
    for (int o = 4; o; o >>= 1) v += __shfl_xor_sync(0xffu, v, o);
    if (threadIdx.x == 0) red[0] = rsqrtf(v / (float)DD + 1e-6f);
  }
  __syncthreads();
  float r = red[0];
  for (int i = threadIdx.x; i < DD; i += 256) out[(size_t)row * DD + i] = w[i] * (xr[i] * r);
}

// ---------------- attention: 2 threads per (q,h), 32 dims each ----------------
// grid (SS/64, HH, BB), 128 threads. Pair (tid, tid^1) shares a query.
__global__ __launch_bounds__(128) void attn_kernel() {
  int tq = threadIdx.x >> 1;
  int half = threadIdx.x & 1;
  int q = blockIdx.x * 64 + tq;
  int h = blockIdx.y;
  int b = blockIdx.z;
  int t = b * SS + q;
  int kv = h / (HH / KVHH);
  const float* qp = g_Q + (size_t)t * DD + h * HDD + half * 32;
  float qr[32];
#pragma unroll
  for (int i = 0; i < 32; i++) qr[i] = qp[i] * 0.125f;
  float acc[32] = {};
  float m = -1e30f, l = 0.f;
  __shared__ float Ks[32][HDD];
  __shared__ float Vs[32][HDD];
  int fr = threadIdx.x >> 2;
  int fc = (threadIdx.x & 3) * 16;
  for (int kt = 0; kt < SS; kt += 32) {
    const float* kp = g_K + (size_t)(b*SS + kt + fr) * (KVHH*HDD) + kv*HDD + fc;
    const float* vp = g_V + (size_t)(b*SS + kt + fr) * (KVHH*HDD) + kv*HDD + fc;
#pragma unroll
    for (int i = 0; i < 4; i++) {
      *(float4*)&Ks[fr][fc + i*4] = *(const float4*)(kp + i*4);
      *(float4*)&Vs[fr][fc + i*4] = *(const float4*)(vp + i*4);
    }
    __syncthreads();
#pragma unroll
    for (int sb = 0; sb < 2; sb++) {
      float sc[16];
#pragma unroll
      for (int j = 0; j < 16; j++) {
        const float* kk = &Ks[sb*16 + j][half*32];
        float s = 0.f;
#pragma unroll
        for (int i = 0; i < 8; i++) {
          float4 k4 = *(const float4*)(kk + i*4);
          s += qr[i*4]*k4.x + qr[i*4+1]*k4.y + qr[i*4+2]*k4.z + qr[i*4+3]*k4.w;
        }
        sc[j] = s + __shfl_xor_sync(0xffffffffu, s, 1);
      }
      float mt = m;
#pragma unroll
      for (int j = 0; j < 16; j++) mt = fmaxf(mt, sc[j]);
      float corr = __expf(m - mt);
      m = mt;
      l *= corr;
#pragma unroll
      for (int i = 0; i < 32; i++) acc[i] *= corr;
#pragma unroll
      for (int j = 0; j < 16; j++) {
        float p = __expf(sc[j] - m);
        l += p;
        const float* vv = &Vs[sb*16 + j][half*32];
#pragma unroll
        for (int i = 0; i < 8; i++) {
          float4 v4 = *(const float4*)(vv + i*4);
          acc[i*4]   += p * v4.x;
          acc[i*4+1] += p * v4.y;
          acc[i*4+2] += p * v4.z;
          acc[i*4+3] += p * v4.w;
        }
      }
    }
    __syncthreads();
  }
  float inv = 1.f / l;
  float* op = g_attn + (size_t)t * DD + h * HDD + half * 32;
#pragma unroll
  for (int i = 0; i < 32; i++) op[i] = acc[i] * inv;
}

// ---------------- MoE routing ------------------------------------------------
__global__ void zero_kernel() { if (threadIdx.x < EE) g_cnt[threadIdx.x] = 0; }

__global__ __launch_bounds__(256) void gate_kernel(const float* __restrict__ gw) {
  int warp = (blockIdx.x * 256 + threadIdx.x) >> 5;
  int lane = threadIdx.x & 31;
  if (warp >= TT) return;
  const float* x = g_h2 + (size_t)warp * DD;
  float acc[EE] = {};
  for (int k = lane; k < DD; k += 32) {
    float xv = x[k];
    const float* g = gw + (size_t)k * EE;
#pragma unroll
    for (int e = 0; e < EE; e++) acc[e] += xv * g[e];
  }
#pragma unroll
  for (int e = 0; e < EE; e++)
#pragma unroll
    for (int o = 16; o; o >>= 1) acc[e] += __shfl_xor_sync(0xffffffffu, acc[e], o);
  if (lane == 0) {
    float mx = acc[0];
#pragma unroll
    for (int e = 1; e < EE; e++) mx = fmaxf(mx, acc[e]);
    float p[EE];
#pragma unroll
    for (int e = 0; e < EE; e++) p[e] = __expf(acc[e] - mx);
    int i0 = 0;
#pragma unroll
    for (int e = 1; e < EE; e++) if (p[e] > p[i0]) i0 = e;
    int i1 = (i0 == 0) ? 1 : 0;
#pragma unroll
    for (int e = 0; e < EE; e++) if (e != i0 && p[e] > p[i1]) i1 = e;
    float w0 = p[i0], w1 = p[i1];
    float inv = 1.f / (w0 + w1);
    w0 *= inv; w1 *= inv;
    g_te[warp*2] = i0; g_te[warp*2+1] = i1;
    g_tw[warp*2] = w0; g_tw[warp*2+1] = w1;
    atomicAdd(&g_cnt[i0], 1);
    atomicAdd(&g_cnt[i1], 1);
  }
}

__global__ void scan_kernel() {
  if (threadIdx.x == 0) {
    int o = 0;
    for (int e = 0; e < EE; e++) { g_off[e] = o; o += g_cnt[e]; g_cur[e] = 0; }
    g_off[EE] = o;
  }
}

__global__ __launch_bounds__(256) void scatter_kernel() {
  int t = blockIdx.x * 256 + threadIdx.x;
  if (t >= TT) return;
#pragma unroll
  for (int k = 0; k < 2; k++) {
    int e = g_te[t*2+k];
    int pos = atomicAdd(&g_cur[e], 1);
    int slot = g_off[e] + pos;
    g_tok[slot] = t;
    g_slotw[slot] = g_tw[t*2+k];
    g_tokslot[t*2+k] = slot;
  }
}

// ---------------- activation: g_act = silu(g_act) * g_h3 ---------------------
__global__ __launch_bounds__(256) void act_kernel() {
  size_t i = ((size_t)blockIdx.x * 256 + threadIdx.x) * 4;
  float4 h1 = *(float4*)(g_act + i);
  float4 h3 = *(const float4*)(g_h3 + i);
  h1.x = h1.x / (1.f + __expf(-h1.x)) * h3.x;
  h1.y = h1.y / (1.f + __expf(-h1.y)) * h3.y;
  h1.z = h1.z / (1.f + __expf(-h1.z)) * h3.z;
  h1.w = h1.w / (1.f + __expf(-h1.w)) * h3.w;
  *(float4*)(g_act + i) = h1;
}

// ---------------- combine ----------------------------------------------------
__global__ __launch_bounds__(256) void combine_kernel(float* __restrict__ outh) {
  int t = blockIdx.x;
  int s0 = g_tokslot[t*2], s1 = g_tokslot[t*2+1];
  int i = threadIdx.x * 4;
  float4 h  = *(float4*)(outh + (size_t)t * DD + i);
  float4 p0 = *(const float4*)(g_part + (size_t)s0 * DD + i);
  float4 p1 = *(const float4*)(g_part + (size_t)s1 * DD + i);
  h.x += p0.x + p1.x; h.y += p0.y + p1.y; h.z += p0.z + p1.z; h.w += p0.w + p1.w;
  *(float4*)(outh + (size_t)t * DD + i) = h;
}

// ---------------- launcher ---------------------------------------------------
extern "C" void kernel_launch(void* const* d_in, const int* in_sizes, int n_in,
                              void* d_out, int out_size) {
  const float* hidden = (const float*)d_in[0];
  const float* prev   = (const float*)d_in[2];
  const float* wq     = (const float*)d_in[3];
  const float* wk     = (const float*)d_in[4];
  const float* wv     = (const float*)d_in[5];
  const float* wo     = (const float*)d_in[6];
  const float* mixw   = (const float*)d_in[7];
  const float* mixb   = (const float*)d_in[8];
  const float* gatew  = (const float*)d_in[9];
  const float* w1     = (const float*)d_in[10];
  const float* w2     = (const float*)d_in[11];
  const float* w3     = (const float*)d_in[12];
  const float* ln1    = (const float*)d_in[13];
  const float* ln2    = (const float*)d_in[14];
  const float* compw  = (const float*)d_in[15];
  const float* compb  = (const float*)d_in[16];

  float* out_h     = (float*)d_out;
  float* out_mixed = out_h + (size_t)TT * DD;
  float* out_comp  = out_mixed + (size_t)TT * DD;

  void *pX, *pQ, *pK, *pV, *pAttn, *pAO, *pH2, *pAct, *pH3, *pPart;
  cudaGetSymbolAddress(&pX, g_X);
  cudaGetSymbolAddress(&pQ, g_Q);
  cudaGetSymbolAddress(&pK, g_K);
  cudaGetSymbolAddress(&pV, g_V);
  cudaGetSymbolAddress(&pAttn, g_attn);
  cudaGetSymbolAddress(&pAO, g_attnout);
  cudaGetSymbolAddress(&pH2, g_h2);
  cudaGetSymbolAddress(&pAct, g_act);
  cudaGetSymbolAddress(&pH3, g_h3);
  cudaGetSymbolAddress(&pPart, g_part);
  float* X = (float*)pX; float* Q = (float*)pQ; float* K = (float*)pK;
  float* V = (float*)pV; float* ATT = (float*)pAttn; float* AO = (float*)pAO;
  float* H2 = (float*)pH2; float* ACT = (float*)pAct; float* H3 = (float*)pH3;
  float* PART = (float*)pPart;

  cudaFuncSetAttribute(gemm_tf32<0>, cudaFuncAttributeMaxDynamicSharedMemorySize, GSMEM);
  cudaFuncSetAttribute(gemm_tf32<1>, cudaFuncAttributeMaxDynamicSharedMemorySize, GSMEM);
  cudaFuncSetAttribute(gemm_tf32<2>, cudaFuncAttributeMaxDynamicSharedMemorySize, GSMEM);
  cudaFuncSetAttribute(gemm_tf32<3>, cudaFuncAttributeMaxDynamicSharedMemorySize, GSMEM);
  cudaFuncSetAttribute(gemm_tf32<4>, cudaFuncAttributeMaxDynamicSharedMemorySize, GSMEM);

  rmsnorm_kernel<<<TT, 256>>>(hidden, ln1, X);
  // fused QKV: N=1536 (8 blocks Q, 2 K, 2 V)
  gemm_tf32<4><<<dim3(12, TT/128), 256, GSMEM>>>(
      X, nullptr, wq, wk, wv, nullptr, nullptr, Q, K, V, DD, DD);
  attn_kernel<<<dim3(SS/64, HH, BB), 128>>>();
  gemm_tf32<0><<<dim3(DD/128, TT/128), 256, GSMEM>>>(
      ATT, nullptr, wo, nullptr, nullptr, nullptr, nullptr, AO, nullptr, nullptr, DD, DD);
  gemm_tf32<1><<<dim3(DD/128, TT/128), 256, GSMEM>>>(
      AO, prev, mixw, nullptr, nullptr, mixb, hidden, out_mixed, out_h, nullptr, 2*DD, DD);
  rmsnorm_kernel<<<TT, 256>>>(out_h, ln2, H2);
  zero_kernel<<<1, 32>>>();
  gate_kernel<<<TT/8, 256>>>(gatew);
  scan_kernel<<<1, 32>>>();
  scatter_kernel<<<TT/256, 256>>>();
  gemm_tf32<2><<<dim3(FFF/128, TT/128, EE), 256, GSMEM>>>(
      H2, nullptr, w1, nullptr, nullptr, nullptr, nullptr, ACT, nullptr, nullptr, DD, FFF);
  gemm_tf32<2><<<dim3(FFF/128, TT/128, EE), 256, GSMEM>>>(
      H2, nullptr, w3, nullptr, nullptr, nullptr, nullptr, H3, nullptr, nullptr, DD, FFF);
  act_kernel<<<(int)(((size_t)NSLOT*FFF)/(256*4)), 256>>>();
  gemm_tf32<3><<<dim3(DD/128, TT/128, EE), 256, GSMEM>>>(
      ACT, nullptr, w2, nullptr, nullptr, nullptr, nullptr, PART, nullptr, nullptr, FFF, DD);
  combine_kernel<<<TT, 256>>>(out_h);
  gemm_tf32<0><<<dim3(CCOMP/128, TT/128), 256, GSMEM>>>(
      out_h, nullptr, compw, nullptr, nullptr, compb, nullptr, out_comp, nullptr, nullptr, DD, CCOMP);
}

// round 5
// speedup vs baseline: 1.0740x; 1.0740x over previous
#include <cuda_runtime.h>
#include <math.h>
#include <stdint.h>

#define BB 4
#define SS 1024
#define DD 1024
#define TT (BB*SS)           // 4096 tokens
#define HH 16
#define KVHH 4
#define HDD 64
#define EE 8
#define FFF 2816
#define CCOMP 256
#define NSLOT (TT*2)

// ---------------- scratch (static device globals) -----------------------------
__device__ float g_X[TT*DD];
__device__ float g_Q[TT*DD];
__device__ float g_K[TT*KVHH*HDD];
__device__ float g_V[TT*KVHH*HDD];
__device__ float g_attn[TT*DD];
__device__ float g_attnout[TT*DD];
__device__ float g_h2[TT*DD];
__device__ float g_act[NSLOT*FFF];      // h1 then silu(h1)*h3 (in-place)
__device__ float g_h3[NSLOT*FFF];
__device__ float g_part[NSLOT*DD];
__device__ int   g_tok[NSLOT];
__device__ float g_slotw[NSLOT];
__device__ int   g_tokslot[TT*2];
__device__ int   g_te[TT*2];
__device__ float g_tw[TT*2];
__device__ int   g_cnt[EE];
__device__ int   g_off[EE+1];
__device__ int   g_cur[EE];

// ---------------- tf32 helpers ----------------------------------------------
__device__ __forceinline__ uint32_t f2tf(float f) {
  uint32_t u;
  asm("cvt.rna.tf32.f32 %0, %1;" : "=r"(u) : "f"(f));
  return u;
}
__device__ __forceinline__ void mma_tf32(float c[4],
    uint32_t a0, uint32_t a1, uint32_t a2, uint32_t a3,
    uint32_t b0, uint32_t b1) {
  asm volatile(
    "mma.sync.aligned.m16n8k8.row.col.f32.tf32.tf32.f32 "
    "{%0,%1,%2,%3},{%4,%5,%6,%7},{%8,%9},{%0,%1,%2,%3};"
    : "+f"(c[0]), "+f"(c[1]), "+f"(c[2]), "+f"(c[3])
    : "r"(a0), "r"(a1), "r"(a2), "r"(a3), "r"(b0), "r"(b1));
}

// ---------------- unified TF32 tensor-core GEMM (R3 core) ---------------------
// Block 128x128, 256 thr = 8 warps (2 warpM x 4 warpN), warp tile 64x32, Kc=32.
// Smem k-major [32][136] (+8 pad => conflict-free frag LDS); f2tf at store;
// register prefetch hides LDG under compute.
// MODE 0: C = A@B (+bias)   MODE 1: mix (A|A2 over K=2048; C=mixed, C2=h)
// MODE 2: MoE gathered rows MODE 3: MoE down (slot rows, slotw scale)
// MODE 4: fused QKV (B/B2/B3 -> C/C2/C3 selected by colBase)
template<int MODE>
__global__ __launch_bounds__(256) void gemm_tf32(
    const float* __restrict__ A, const float* __restrict__ A2,
    const float* __restrict__ B, const float* __restrict__ B2,
    const float* __restrict__ B3, const float* __restrict__ bias,
    const float* __restrict__ hidden, float* __restrict__ C,
    float* __restrict__ C2, float* __restrict__ C3, int K, int N) {
  __shared__ uint32_t As[32][136];
  __shared__ uint32_t Bs[32][136];

  int base = 0, cnt = 0;
  if (MODE == 2 || MODE == 3) {
    int e = blockIdx.z;
    base = g_off[e];
    cnt = g_off[e+1] - base;
    if ((int)(blockIdx.y * 128) >= cnt) return;
    B += (size_t)e * K * N;
  }
  int rowBase = blockIdx.y * 128;
  int colBase = blockIdx.x * 128;
  int tid = threadIdx.x;
  int lane = tid & 31;
  int warp = tid >> 5;
  int warpM = warp & 1;
  int warpN = warp >> 1;

  // MODE 4 column-range select
  const float* Bsel = B;
  float* Csel = C;
  int bN = N, cOff = 0;
  if (MODE == 4) {
    if (colBase < DD)            { Bsel = B;  Csel = C;  bN = DD;  cOff = 0; }
    else if (colBase < DD + 256) { Bsel = B2; Csel = C2; bN = 256; cOff = DD; }
    else                         { Bsel = B3; Csel = C3; bN = 256; cOff = DD + 256; }
  }

  int am = tid >> 1;            // A fill row 0..127
  const float* arow0 = nullptr;
  const float* arow1 = nullptr;
  if (MODE == 0 || MODE == 4) {
    arow0 = A + (size_t)(rowBase + am) * K;
  } else if (MODE == 1) {
    arow0 = A  + (size_t)(rowBase + am) * DD;
    arow1 = A2 + (size_t)(rowBase + am) * DD;
  } else if (MODE == 2) {
    int rr = rowBase + am; if (rr > cnt - 1) rr = cnt - 1;
    arow0 = A + (size_t)g_tok[base + rr] * K;
  } else {
    int rr = rowBase + am; if (rr > cnt - 1) rr = cnt - 1;
    arow0 = A + (size_t)(base + rr) * K;
  }
  int acol = (tid & 1) * 16;

  int bk = tid >> 3;            // B fill row 0..31
  int bc = (tid & 7) * 4;
  const float* brow = Bsel + (size_t)bk * bN + (colBase - cOff) + bc;

  float4 pa[4], pb[4];
  auto ldA = [&](int k0) {
#pragma unroll
    for (int j = 0; j < 4; j++) {
      const float* p = arow0;
      int kk = k0 + acol + j * 4;
      if (MODE == 1 && kk >= DD) { p = arow1; kk -= DD; }
      pa[j] = *(const float4*)(p + kk);
    }
  };
  auto ldB = [&](int k0) {
#pragma unroll
    for (int j = 0; j < 4; j++)
      pb[j] = *(const float4*)(brow + (size_t)k0 * bN + j * 32);
  };
  auto stA = [&]() {
#pragma unroll
    for (int j = 0; j < 4; j++) {
      int c = acol + j * 4;
      As[c  ][am] = f2tf(pa[j].x);
      As[c+1][am] = f2tf(pa[j].y);
      As[c+2][am] = f2tf(pa[j].z);
      As[c+3][am] = f2tf(pa[j].w);
    }
  };
  auto stB = [&]() {
#pragma unroll
    for (int j = 0; j < 4; j++) {
      int c = bc + j * 32;
      Bs[bk][c  ] = f2tf(pb[j].x);
      Bs[bk][c+1] = f2tf(pb[j].y);
      Bs[bk][c+2] = f2tf(pb[j].z);
      Bs[bk][c+3] = f2tf(pb[j].w);
    }
  };

  float acc[4][4][4] = {};
  int kq = lane & 3;
  int mq = lane >> 2;

  ldA(0); ldB(0);
  stA(); stB();
  __syncthreads();
  for (int k0 = 0; k0 < K; k0 += 32) {
    bool more = (k0 + 32) < K;
    if (more) { ldA(k0 + 32); ldB(k0 + 32); }
#pragma unroll
    for (int kc = 0; kc < 4; kc++) {
      int kb = kc * 8;
      uint32_t af[4][4];
#pragma unroll
      for (int mt = 0; mt < 4; mt++) {
        int mb = warpM * 64 + mt * 16 + mq;
        af[mt][0] = As[kb + kq    ][mb];
        af[mt][1] = As[kb + kq    ][mb + 8];
        af[mt][2] = As[kb + kq + 4][mb];
        af[mt][3] = As[kb + kq + 4][mb + 8];
      }
      uint32_t bf[4][2];
#pragma unroll
      for (int nt = 0; nt < 4; nt++) {
        int nb = warpN * 32 + nt * 8 + mq;
        bf[nt][0] = Bs[kb + kq    ][nb];
        bf[nt][1] = Bs[kb + kq + 4][nb];
      }
#pragma unroll
      for (int mt = 0; mt < 4; mt++)
#pragma unroll
        for (int nt = 0; nt < 4; nt++)
          mma_tf32(acc[mt][nt], af[mt][0], af[mt][1], af[mt][2], af[mt][3],
                   bf[nt][0], bf[nt][1]);
    }
    __syncthreads();
    if (more) { stA(); stB(); __syncthreads(); }
  }

  // ---- epilogue ----
#pragma unroll
  for (int mt = 0; mt < 4; mt++) {
#pragma unroll
    for (int half = 0; half < 2; half++) {
      int r = rowBase + warpM * 64 + mt * 16 + mq + half * 8;
#pragma unroll
      for (int nt = 0; nt < 4; nt++) {
        int n = colBase + warpN * 32 + nt * 8 + 2 * kq;
        float v0 = acc[mt][nt][half * 2];
        float v1 = acc[mt][nt][half * 2 + 1];
        if (MODE == 0) {
          if (bias) { v0 += bias[n]; v1 += bias[n + 1]; }
          *(float2*)(C + (size_t)r * N + n) = make_float2(v0, v1);
        } else if (MODE == 1) {
          v0 += bias[n]; v1 += bias[n + 1];
          *(float2*)(C + (size_t)r * N + n) = make_float2(v0, v1);
          float h0 = hidden[(size_t)r * N + n];
          float h1 = hidden[(size_t)r * N + n + 1];
          *(float2*)(C2 + (size_t)r * N + n) = make_float2(h0 + v0, h1 + v1);
        } else if (MODE == 2) {
          if (r < cnt)
            *(float2*)(C + (size_t)(base + r) * N + n) = make_float2(v0, v1);
        } else if (MODE == 3) {
          if (r < cnt) {
            float w = g_slotw[base + r];
            *(float2*)(C + (size_t)(base + r) * N + n) = make_float2(w*v0, w*v1);
          }
        } else {  // MODE 4
          *(float2*)(Csel + (size_t)r * bN + (n - cOff)) = make_float2(v0, v1);
        }
      }
    }
  }
}

// ---------------- rmsnorm ----------------------------------------------------
__global__ __launch_bounds__(256) void rmsnorm_kernel(
    const float* __restrict__ x, const float* __restrict__ w, float* __restrict__ out) {
  int row = blockIdx.x;
  const float* xr = x + (size_t)row * DD;
  float ss = 0.f;
  for (int i = threadIdx.x; i < DD; i += 256) { float v = xr[i]; ss += v * v; }
  __shared__ float red[8];
#pragma unroll
  for (int o = 16; o; o >>= 1) ss += __shfl_xor_sync(0xffffffffu, ss, o);
  if ((threadIdx.x & 31) == 0) red[threadIdx.x >> 5] = ss;
  __syncthreads();
  if (threadIdx.x < 8) {
    float v = red[threadIdx.x];
#pragma unroll
    for (int o = 4; o; o >>= 1) v += __shfl_xor_sync(0xffu, v, o);
    if (threadIdx.x == 0) red[0] = rsqrtf(v / (float)DD + 1e-6f);
  }
  __syncthreads();
  float r = red[0];
  for (int i = threadIdx.x; i < DD; i += 256) out[(size_t)row * DD + i] = w[i] * (xr[i] * r);
}

// ---------------- attention: 2 threads per (q,h), 32 dims each ----------------
// grid (SS/64, HH, BB), 128 threads. Pair (tid, tid^1) shares a query.
__global__ __launch_bounds__(128) void attn_kernel() {
  int tq = threadIdx.x >> 1;
  int half = threadIdx.x & 1;
  int q = blockIdx.x * 64 + tq;
  int h = blockIdx.y;
  int b = blockIdx.z;
  int t = b * SS + q;
  int kv = h / (HH / KVHH);
  const float* qp = g_Q + (size_t)t * DD + h * HDD + half * 32;
  float qr[32];
#pragma unroll
  for (int i = 0; i < 32; i++) qr[i] = qp[i] * 0.125f;
  float acc[32] = {};
  float m = -1e30f, l = 0.f;
  __shared__ float Ks[32][HDD];
  __shared__ float Vs[32][HDD];
  int fr = threadIdx.x >> 2;
  int fc = (threadIdx.x & 3) * 16;
  for (int kt = 0; kt < SS; kt += 32) {
    const float* kp = g_K + (size_t)(b*SS + kt + fr) * (KVHH*HDD) + kv*HDD + fc;
    const float* vp = g_V + (size_t)(b*SS + kt + fr) * (KVHH*HDD) + kv*HDD + fc;
#pragma unroll
    for (int i = 0; i < 4; i++) {
      *(float4*)&Ks[fr][fc + i*4] = *(const float4*)(kp + i*4);
      *(float4*)&Vs[fr][fc + i*4] = *(const float4*)(vp + i*4);
    }
    __syncthreads();
#pragma unroll
    for (int sb = 0; sb < 2; sb++) {
      float sc[16];
#pragma unroll
      for (int j = 0; j < 16; j++) {
        const float* kk = &Ks[sb*16 + j][half*32];
        float s = 0.f;
#pragma unroll
        for (int i = 0; i < 8; i++) {
          float4 k4 = *(const float4*)(kk + i*4);
          s += qr[i*4]*k4.x + qr[i*4+1]*k4.y + qr[i*4+2]*k4.z + qr[i*4+3]*k4.w;
        }
        sc[j] = s + __shfl_xor_sync(0xffffffffu, s, 1);
      }
      float mt = m;
#pragma unroll
      for (int j = 0; j < 16; j++) mt = fmaxf(mt, sc[j]);
      float corr = __expf(m - mt);
      m = mt;
      l *= corr;
#pragma unroll
      for (int i = 0; i < 32; i++) acc[i] *= corr;
#pragma unroll
      for (int j = 0; j < 16; j++) {
        float p = __expf(sc[j] - m);
        l += p;
        const float* vv = &Vs[sb*16 + j][half*32];
#pragma unroll
        for (int i = 0; i < 8; i++) {
          float4 v4 = *(const float4*)(vv + i*4);
          acc[i*4]   += p * v4.x;
          acc[i*4+1] += p * v4.y;
          acc[i*4+2] += p * v4.z;
          acc[i*4+3] += p * v4.w;
        }
      }
    }
    __syncthreads();
  }
  float inv = 1.f / l;
  float* op = g_attn + (size_t)t * DD + h * HDD + half * 32;
#pragma unroll
  for (int i = 0; i < 32; i++) op[i] = acc[i] * inv;
}

// ---------------- MoE routing ------------------------------------------------
__global__ void zero_kernel() { if (threadIdx.x < EE) g_cnt[threadIdx.x] = 0; }

__global__ __launch_bounds__(256) void gate_kernel(const float* __restrict__ gw) {
  int warp = (blockIdx.x * 256 + threadIdx.x) >> 5;
  int lane = threadIdx.x & 31;
  if (warp >= TT) return;
  const float* x = g_h2 + (size_t)warp * DD;
  float acc[EE] = {};
  for (int k = lane; k < DD; k += 32) {
    float xv = x[k];
    const float* g = gw + (size_t)k * EE;
#pragma unroll
    for (int e = 0; e < EE; e++) acc[e] += xv * g[e];
  }
#pragma unroll
  for (int e = 0; e < EE; e++)
#pragma unroll
    for (int o = 16; o; o >>= 1) acc[e] += __shfl_xor_sync(0xffffffffu, acc[e], o);
  if (lane == 0) {
    float mx = acc[0];
#pragma unroll
    for (int e = 1; e < EE; e++) mx = fmaxf(mx, acc[e]);
    float p[EE];
#pragma unroll
    for (int e = 0; e < EE; e++) p[e] = __expf(acc[e] - mx);
    int i0 = 0;
#pragma unroll
    for (int e = 1; e < EE; e++) if (p[e] > p[i0]) i0 = e;
    int i1 = (i0 == 0) ? 1 : 0;
#pragma unroll
    for (int e = 0; e < EE; e++) if (e != i0 && p[e] > p[i1]) i1 = e;
    float w0 = p[i0], w1 = p[i1];
    float inv = 1.f / (w0 + w1);
    w0 *= inv; w1 *= inv;
    g_te[warp*2] = i0; g_te[warp*2+1] = i1;
    g_tw[warp*2] = w0; g_tw[warp*2+1] = w1;
    atomicAdd(&g_cnt[i0], 1);
    atomicAdd(&g_cnt[i1], 1);
  }
}

__global__ void scan_kernel() {
  if (threadIdx.x == 0) {
    int o = 0;
    for (int e = 0; e < EE; e++) { g_off[e] = o; o += g_cnt[e]; g_cur[e] = 0; }
    g_off[EE] = o;
  }
}

__global__ __launch_bounds__(256) void scatter_kernel() {
  int t = blockIdx.x * 256 + threadIdx.x;
  if (t >= TT) return;
#pragma unroll
  for (int k = 0; k < 2; k++) {
    int e = g_te[t*2+k];
    int pos = atomicAdd(&g_cur[e], 1);
    int slot = g_off[e] + pos;
    g_tok[slot] = t;
    g_slotw[slot] = g_tw[t*2+k];
    g_tokslot[t*2+k] = slot;
  }
}

// ---------------- activation: g_act = silu(g_act) * g_h3 ---------------------
__global__ __launch_bounds__(256) void act_kernel() {
  size_t i = ((size_t)blockIdx.x * 256 + threadIdx.x) * 4;
  float4 h1 = *(float4*)(g_act + i);
  float4 h3 = *(const float4*)(g_h3 + i);
  h1.x = h1.x / (1.f + __expf(-h1.x)) * h3.x;
  h1.y = h1.y / (1.f + __expf(-h1.y)) * h3.y;
  h1.z = h1.z / (1.f + __expf(-h1.z)) * h3.z;
  h1.w = h1.w / (1.f + __expf(-h1.w)) * h3.w;
  *(float4*)(g_act + i) = h1;
}

// ---------------- combine ----------------------------------------------------
__global__ __launch_bounds__(256) void combine_kernel(float* __restrict__ outh) {
  int t = blockIdx.x;
  int s0 = g_tokslot[t*2], s1 = g_tokslot[t*2+1];
  int i = threadIdx.x * 4;
  float4 h  = *(float4*)(outh + (size_t)t * DD + i);
  float4 p0 = *(const float4*)(g_part + (size_t)s0 * DD + i);
  float4 p1 = *(const float4*)(g_part + (size_t)s1 * DD + i);
  h.x += p0.x + p1.x; h.y += p0.y + p1.y; h.z += p0.z + p1.z; h.w += p0.w + p1.w;
  *(float4*)(outh + (size_t)t * DD + i) = h;
}

// ---------------- launcher ---------------------------------------------------
extern "C" void kernel_launch(void* const* d_in, const int* in_sizes, int n_in,
                              void* d_out, int out_size) {
  const float* hidden = (const float*)d_in[0];
  const float* prev   = (const float*)d_in[2];
  const float* wq     = (const float*)d_in[3];
  const float* wk     = (const float*)d_in[4];
  const float* wv     = (const float*)d_in[5];
  const float* wo     = (const float*)d_in[6];
  const float* mixw   = (const float*)d_in[7];
  const float* mixb   = (const float*)d_in[8];
  const float* gatew  = (const float*)d_in[9];
  const float* w1     = (const float*)d_in[10];
  const float* w2     = (const float*)d_in[11];
  const float* w3     = (const float*)d_in[12];
  const float* ln1    = (const float*)d_in[13];
  const float* ln2    = (const float*)d_in[14];
  const float* compw  = (const float*)d_in[15];
  const float* compb  = (const float*)d_in[16];

  float* out_h     = (float*)d_out;
  float* out_mixed = out_h + (size_t)TT * DD;
  float* out_comp  = out_mixed + (size_t)TT * DD;

  void *pX, *pQ, *pK, *pV, *pAttn, *pAO, *pH2, *pAct, *pH3, *pPart;
  cudaGetSymbolAddress(&pX, g_X);
  cudaGetSymbolAddress(&pQ, g_Q);
  cudaGetSymbolAddress(&pK, g_K);
  cudaGetSymbolAddress(&pV, g_V);
  cudaGetSymbolAddress(&pAttn, g_attn);
  cudaGetSymbolAddress(&pAO, g_attnout);
  cudaGetSymbolAddress(&pH2, g_h2);
  cudaGetSymbolAddress(&pAct, g_act);
  cudaGetSymbolAddress(&pH3, g_h3);
  cudaGetSymbolAddress(&pPart, g_part);
  float* X = (float*)pX; float* Q = (float*)pQ; float* K = (float*)pK;
  float* V = (float*)pV; float* ATT = (float*)pAttn; float* AO = (float*)pAO;
  float* H2 = (float*)pH2; float* ACT = (float*)pAct; float* H3 = (float*)pH3;
  float* PART = (float*)pPart;

  rmsnorm_kernel<<<TT, 256>>>(hidden, ln1, X);
  // fused QKV: N=1536 (8 blocks Q, 2 K, 2 V)
  gemm_tf32<4><<<dim3(12, TT/128), 256>>>(
      X, nullptr, wq, wk, wv, nullptr, nullptr, Q, K, V, DD, DD);
  attn_kernel<<<dim3(SS/64, HH, BB), 128>>>();
  gemm_tf32<0><<<dim3(DD/128, TT/128), 256>>>(
      ATT, nullptr, wo, nullptr, nullptr, nullptr, nullptr, AO, nullptr, nullptr, DD, DD);
  gemm_tf32<1><<<dim3(DD/128, TT/128), 256>>>(
      AO, prev, mixw, nullptr, nullptr, mixb, hidden, out_mixed, out_h, nullptr, 2*DD, DD);
  rmsnorm_kernel<<<TT, 256>>>(out_h, ln2, H2);
  zero_kernel<<<1, 32>>>();
  gate_kernel<<<TT/8, 256>>>(gatew);
  scan_kernel<<<1, 32>>>();
  scatter_kernel<<<TT/256, 256>>>();
  gemm_tf32<2><<<dim3(FFF/128, TT/128, EE), 256>>>(
      H2, nullptr, w1, nullptr, nullptr, nullptr, nullptr, ACT, nullptr, nullptr, DD, FFF);
  gemm_tf32<2><<<dim3(FFF/128, TT/128, EE), 256>>>(
      H2, nullptr, w3, nullptr, nullptr, nullptr, nullptr, H3, nullptr, nullptr, DD, FFF);
  act_kernel<<<(int)(((size_t)NSLOT*FFF)/(256*4)), 256>>>();
  gemm_tf32<3><<<dim3(DD/128, TT/128, EE), 256>>>(
      ACT, nullptr, w2, nullptr, nullptr, nullptr, nullptr, PART, nullptr, nullptr, FFF, DD);
  combine_kernel<<<TT, 256>>>(out_h);
  gemm_tf32<0><<<dim3(CCOMP/128, TT/128), 256>>>(
      out_h, nullptr, compw, nullptr, nullptr, compb, nullptr, out_comp, nullptr, nullptr, DD, CCOMP);
}

// round 6
// speedup vs baseline: 1.4666x; 1.3655x over previous
#include <cuda_runtime.h>
#include <cuda_fp16.h>
#include <math.h>
#include <stdint.h>

#define BB 4
#define SS 1024
#define DD 1024
#define TT (BB*SS)           // 4096 tokens
#define HH 16
#define KVHH 4
#define HDD 64
#define EE 8
#define FFF 2816
#define CCOMP 256
#define NSLOT (TT*2)

// ---------------- scratch (static device globals) -----------------------------
__device__ float g_X[TT*DD];
__device__ float g_Q[TT*DD];
__device__ float g_K[TT*KVHH*HDD];
__device__ float g_V[TT*KVHH*HDD];
__device__ float g_attn[TT*DD];
__device__ float g_attnout[TT*DD];
__device__ float g_h2[TT*DD];
__device__ float g_act[NSLOT*FFF];      // h1 then silu(h1)*h3 (in-place)
__device__ float g_h3[NSLOT*FFF];
__device__ float g_part[NSLOT*DD];
__device__ int   g_tok[NSLOT];
__device__ float g_slotw[NSLOT];
__device__ int   g_tokslot[TT*2];
__device__ int   g_te[TT*2];
__device__ float g_tw[TT*2];
__device__ int   g_cnt[EE];
__device__ int   g_off[EE+1];
__device__ int   g_cur[EE];

// ---------------- fp16 helpers ------------------------------------------------
__device__ __forceinline__ uint32_t f2h2(float lo, float hi) {
  __half2 h = __floats2half2_rn(lo, hi);
  return *(uint32_t*)&h;
}
__device__ __forceinline__ void mma_f16(float c[4],
    uint32_t a0, uint32_t a1, uint32_t a2, uint32_t a3,
    uint32_t b0, uint32_t b1) {
  asm volatile(
    "mma.sync.aligned.m16n8k16.row.col.f32.f16.f16.f32 "
    "{%0,%1,%2,%3},{%4,%5,%6,%7},{%8,%9},{%0,%1,%2,%3};"
    : "+f"(c[0]), "+f"(c[1]), "+f"(c[2]), "+f"(c[3])
    : "r"(a0), "r"(a1), "r"(a2), "r"(a3), "r"(b0), "r"(b1));
}

// ---------------- unified FP16 tensor-core GEMM -------------------------------
// Block 128x128, 256 thr = 8 warps (2 warpM x 4 warpN), warp tile 64x32.
// K chunk 32 = 2 x m16n8k16 steps. fp32 accum. Double-buffered smem,
// ONE __syncthreads per chunk. f32->f16x2 pack at fill time.
// A smem: [stage][m=128][kk=16+4pad] uint32 (half2, lo = even k). W=20 ->
//   fragment banks (20*mq+kq) mod 32 all distinct: conflict-free.
// B smem: [stage][kk=16][n=128+8pad] uint32 (half2 of rows 2kk,2kk+1). W=136 ->
//   fragment banks (8*kq+nb) mod 32 all distinct: conflict-free.
// MODE 0: C = A@B (+bias)   MODE 1: mix (A|A2 over K=2048; C=mixed, C2=h)
// MODE 2: MoE gathered rows MODE 3: MoE down (slot rows, slotw scale)
// MODE 4: fused QKV (B/B2/B3 -> C/C2/C3 selected by colBase)
template<int MODE>
__global__ __launch_bounds__(256, 2) void gemm_h(
    const float* __restrict__ A, const float* __restrict__ A2,
    const float* __restrict__ B, const float* __restrict__ B2,
    const float* __restrict__ B3, const float* __restrict__ bias,
    const float* __restrict__ hidden, float* __restrict__ C,
    float* __restrict__ C2, float* __restrict__ C3, int K, int N) {
  __shared__ uint32_t As[2][128][20];
  __shared__ uint32_t Bs[2][16][136];

  int base = 0, cnt = 0;
  if (MODE == 2 || MODE == 3) {
    int e = blockIdx.z;
    base = g_off[e];
    cnt = g_off[e+1] - base;
    if ((int)(blockIdx.y * 128) >= cnt) return;
    B += (size_t)e * K * N;
  }
  int rowBase = blockIdx.y * 128;
  int colBase = blockIdx.x * 128;
  int tid = threadIdx.x;
  int lane = tid & 31;
  int warp = tid >> 5;
  int warpM = warp & 1;
  int warpN = warp >> 1;

  // MODE 4 column-range select
  const float* Bsel = B;
  float* Csel = C;
  int bN = N, cOff = 0;
  if (MODE == 4) {
    if (colBase < DD)            { Bsel = B;  Csel = C;  bN = DD;  cOff = 0; }
    else if (colBase < DD + 256) { Bsel = B2; Csel = C2; bN = 256; cOff = DD; }
    else                         { Bsel = B3; Csel = C3; bN = 256; cOff = DD + 256; }
  }

  // ---- A fill: thread row am=tid>>1, k-half ah=tid&1 (16 floats/chunk) ----
  int am = tid >> 1;
  int ah = tid & 1;
  const float* arow0 = nullptr;
  const float* arow1 = nullptr;
  if (MODE == 0 || MODE == 4) {
    arow0 = A + (size_t)(rowBase + am) * K;
  } else if (MODE == 1) {
    arow0 = A  + (size_t)(rowBase + am) * DD;
    arow1 = A2 + (size_t)(rowBase + am) * DD;
  } else if (MODE == 2) {
    int rr = rowBase + am; if (rr > cnt - 1) rr = cnt - 1;
    arow0 = A + (size_t)g_tok[base + rr] * K;
  } else {
    int rr = rowBase + am; if (rr > cnt - 1) rr = cnt - 1;
    arow0 = A + (size_t)(base + rr) * K;
  }

  // ---- B fill: thread k-pair row bkk=tid>>4, cols bc..bc+7 -----------------
  int bkk = tid >> 4;           // 0..15
  int bc = (tid & 15) * 8;
  const float* bptr = Bsel + (colBase - cOff) + bc;

  float4 pa[4], pb[4];
  auto ldA = [&](int k0) {
#pragma unroll
    for (int j = 0; j < 4; j++) {
      const float* p = arow0;
      int kk = k0 + ah * 16 + j * 4;
      if (MODE == 1 && kk >= DD) { p = arow1; kk -= DD; }
      pa[j] = *(const float4*)(p + kk);
    }
  };
  auto ldB = [&](int k0) {
    const float* r0 = bptr + (size_t)(k0 + 2*bkk) * bN;
    const float* r1 = r0 + bN;
    pb[0] = *(const float4*)(r0);
    pb[1] = *(const float4*)(r0 + 4);
    pb[2] = *(const float4*)(r1);
    pb[3] = *(const float4*)(r1 + 4);
  };
  auto stA = [&](int st) {
    uint32_t q[8];
#pragma unroll
    for (int j = 0; j < 4; j++) {
      q[2*j]   = f2h2(pa[j].x, pa[j].y);
      q[2*j+1] = f2h2(pa[j].z, pa[j].w);
    }
    *(uint4*)&As[st][am][ah*8]     = *(uint4*)&q[0];
    *(uint4*)&As[st][am][ah*8 + 4] = *(uint4*)&q[4];
  };
  auto stB = [&](int st) {
    uint32_t q[8];
    float* lo = (float*)&pb[0];   // pb0,pb1 = row 2bkk cols 0..7
    float* hi = (float*)&pb[2];   // pb2,pb3 = row 2bkk+1 cols 0..7
#pragma unroll
    for (int i = 0; i < 8; i++) q[i] = f2h2(lo[i], hi[i]);
    *(uint4*)&Bs[st][bkk][bc]     = *(uint4*)&q[0];
    *(uint4*)&Bs[st][bkk][bc + 4] = *(uint4*)&q[4];
  };

  float acc[4][4][4] = {};
  int kq = lane & 3;
  int mq = lane >> 2;
  int nch = K / 32;

  ldA(0); ldB(0);
  stA(0); stB(0);
  __syncthreads();
  for (int i = 0; i < nch; i++) {
    bool more = (i + 1) < nch;
    if (more) { ldA((i+1) * 32); ldB((i+1) * 32); }
    int st = i & 1;
#pragma unroll
    for (int kc = 0; kc < 2; kc++) {
      int kb = kc * 8;
      uint32_t af[4][4];
#pragma unroll
      for (int mt = 0; mt < 4; mt++) {
        int mb = warpM * 64 + mt * 16 + mq;
        af[mt][0] = As[st][mb    ][kb + kq    ];
        af[mt][1] = As[st][mb + 8][kb + kq    ];
        af[mt][2] = As[st][mb    ][kb + kq + 4];
        af[mt][3] = As[st][mb + 8][kb + kq + 4];
      }
      uint32_t bf[4][2];
#pragma unroll
      for (int nt = 0; nt < 4; nt++) {
        int nb = warpN * 32 + nt * 8 + mq;
        bf[nt][0] = Bs[st][kb + kq    ][nb];
        bf[nt][1] = Bs[st][kb + kq + 4][nb];
      }
#pragma unroll
      for (int mt = 0; mt < 4; mt++)
#pragma unroll
        for (int nt = 0; nt < 4; nt++)
          mma_f16(acc[mt][nt], af[mt][0], af[mt][1], af[mt][2], af[mt][3],
                  bf[nt][0], bf[nt][1]);
    }
    if (more) { stA(st ^ 1); stB(st ^ 1); }
    __syncthreads();
  }

  // ---- epilogue ----
#pragma unroll
  for (int mt = 0; mt < 4; mt++) {
#pragma unroll
    for (int half = 0; half < 2; half++) {
      int r = rowBase + warpM * 64 + mt * 16 + mq + half * 8;
#pragma unroll
      for (int nt = 0; nt < 4; nt++) {
        int n = colBase + warpN * 32 + nt * 8 + 2 * kq;
        float v0 = acc[mt][nt][half * 2];
        float v1 = acc[mt][nt][half * 2 + 1];
        if (MODE == 0) {
          if (bias) { v0 += bias[n]; v1 += bias[n + 1]; }
          *(float2*)(C + (size_t)r * N + n) = make_float2(v0, v1);
        } else if (MODE == 1) {
          v0 += bias[n]; v1 += bias[n + 1];
          *(float2*)(C + (size_t)r * N + n) = make_float2(v0, v1);
          float h0 = hidden[(size_t)r * N + n];
          float h1 = hidden[(size_t)r * N + n + 1];
          *(float2*)(C2 + (size_t)r * N + n) = make_float2(h0 + v0, h1 + v1);
        } else if (MODE == 2) {
          if (r < cnt)
            *(float2*)(C + (size_t)(base + r) * N + n) = make_float2(v0, v1);
        } else if (MODE == 3) {
          if (r < cnt) {
            float w = g_slotw[base + r];
            *(float2*)(C + (size_t)(base + r) * N + n) = make_float2(w*v0, w*v1);
          }
        } else {  // MODE 4
          *(float2*)(Csel + (size_t)r * bN + (n - cOff)) = make_float2(v0, v1);
        }
      }
    }
  }
}

// ---------------- rmsnorm ----------------------------------------------------
__global__ __launch_bounds__(256) void rmsnorm_kernel(
    const float* __restrict__ x, const float* __restrict__ w, float* __restrict__ out) {
  int row = blockIdx.x;
  const float* xr = x + (size_t)row * DD;
  float ss = 0.f;
  for (int i = threadIdx.x; i < DD; i += 256) { float v = xr[i]; ss += v * v; }
  __shared__ float red[8];
#pragma unroll
  for (int o = 16; o; o >>= 1) ss += __shfl_xor_sync(0xffffffffu, ss, o);
  if ((threadIdx.x & 31) == 0) red[threadIdx.x >> 5] = ss;
  __syncthreads();
  if (threadIdx.x < 8) {
    float v = red[threadIdx.x];
#pragma unroll
    for (int o = 4; o; o >>= 1) v += __shfl_xor_sync(0xffu, v, o);
    if (threadIdx.x == 0) red[0] = rsqrtf(v / (float)DD + 1e-6f);
  }
  __syncthreads();
  float r = red[0];
  for (int i = threadIdx.x; i < DD; i += 256) out[(size_t)row * DD + i] = w[i] * (xr[i] * r);
}

// ---------------- attention (R3 proven version: 1 thread/query) --------------
__global__ __launch_bounds__(128) void attn_kernel() {
  int q = blockIdx.x * 128 + threadIdx.x;
  int h = blockIdx.y;
  int b = blockIdx.z;
  int t = b * SS + q;
  int kv = h / (HH / KVHH);
  const float* qp = g_Q + (size_t)t * DD + h * HDD;
  float qr[HDD];
#pragma unroll
  for (int i = 0; i < HDD; i++) qr[i] = qp[i] * 0.125f;
  float acc[HDD] = {};
  float m = -1e30f, l = 0.f;
  __shared__ float Ks[32][HDD];
  __shared__ float Vs[32][HDD];
  int lr = threadIdx.x >> 2;
  int lc = (threadIdx.x & 3) * 16;
  for (int kt = 0; kt < SS; kt += 32) {
    const float* kp = g_K + (size_t)(b*SS + kt + lr) * (KVHH*HDD) + kv*HDD + lc;
    const float* vp = g_V + (size_t)(b*SS + kt + lr) * (KVHH*HDD) + kv*HDD + lc;
#pragma unroll
    for (int i = 0; i < 4; i++) {
      *(float4*)&Ks[lr][lc + i*4] = *(const float4*)(kp + i*4);
      *(float4*)&Vs[lr][lc + i*4] = *(const float4*)(vp + i*4);
    }
    __syncthreads();
    float sc[32];
#pragma unroll
    for (int j = 0; j < 32; j++) {
      float s = 0.f;
#pragma unroll
      for (int i = 0; i < HDD/4; i++) {
        float4 k4 = *(const float4*)&Ks[j][i*4];
        s += qr[i*4]*k4.x + qr[i*4+1]*k4.y + qr[i*4+2]*k4.z + qr[i*4+3]*k4.w;
      }
      sc[j] = s;
    }
    float mt = m;
#pragma unroll
    for (int j = 0; j < 32; j++) mt = fmaxf(mt, sc[j]);
    float corr = __expf(m - mt);
    m = mt;
    l *= corr;
#pragma unroll
    for (int i = 0; i < HDD; i++) acc[i] *= corr;
#pragma unroll
    for (int j = 0; j < 32; j++) {
      float p = __expf(sc[j] - m);
      l += p;
#pragma unroll
      for (int i = 0; i < HDD/4; i++) {
        float4 v4 = *(const float4*)&Vs[j][i*4];
        acc[i*4]   += p * v4.x;
        acc[i*4+1] += p * v4.y;
        acc[i*4+2] += p * v4.z;
        acc[i*4+3] += p * v4.w;
      }
    }
    __syncthreads();
  }
  float inv = 1.f / l;
  float* op = g_attn + (size_t)t * DD + h * HDD;
#pragma unroll
  for (int i = 0; i < HDD; i++) op[i] = acc[i] * inv;
}

// ---------------- MoE routing ------------------------------------------------
__global__ void zero_kernel() { if (threadIdx.x < EE) g_cnt[threadIdx.x] = 0; }

__global__ __launch_bounds__(256) void gate_kernel(const float* __restrict__ gw) {
  int warp = (blockIdx.x * 256 + threadIdx.x) >> 5;
  int lane = threadIdx.x & 31;
  if (warp >= TT) return;
  const float* x = g_h2 + (size_t)warp * DD;
  float acc[EE] = {};
  for (int k = lane; k < DD; k += 32) {
    float xv = x[k];
    const float* g = gw + (size_t)k * EE;
#pragma unroll
    for (int e = 0; e < EE; e++) acc[e] += xv * g[e];
  }
#pragma unroll
  for (int e = 0; e < EE; e++)
#pragma unroll
    for (int o = 16; o; o >>= 1) acc[e] += __shfl_xor_sync(0xffffffffu, acc[e], o);
  if (lane == 0) {
    float mx = acc[0];
#pragma unroll
    for (int e = 1; e < EE; e++) mx = fmaxf(mx, acc[e]);
    float p[EE];
#pragma unroll
    for (int e = 0; e < EE; e++) p[e] = __expf(acc[e] - mx);
    int i0 = 0;
#pragma unroll
    for (int e = 1; e < EE; e++) if (p[e] > p[i0]) i0 = e;
    int i1 = (i0 == 0) ? 1 : 0;
#pragma unroll
    for (int e = 0; e < EE; e++) if (e != i0 && p[e] > p[i1]) i1 = e;
    float w0 = p[i0], w1 = p[i1];
    float inv = 1.f / (w0 + w1);
    w0 *= inv; w1 *= inv;
    g_te[warp*2] = i0; g_te[warp*2+1] = i1;
    g_tw[warp*2] = w0; g_tw[warp*2+1] = w1;
    atomicAdd(&g_cnt[i0], 1);
    atomicAdd(&g_cnt[i1], 1);
  }
}

__global__ void scan_kernel() {
  if (threadIdx.x == 0) {
    int o = 0;
    for (int e = 0; e < EE; e++) { g_off[e] = o; o += g_cnt[e]; g_cur[e] = 0; }
    g_off[EE] = o;
  }
}

__global__ __launch_bounds__(256) void scatter_kernel() {
  int t = blockIdx.x * 256 + threadIdx.x;
  if (t >= TT) return;
#pragma unroll
  for (int k = 0; k < 2; k++) {
    int e = g_te[t*2+k];
    int pos = atomicAdd(&g_cur[e], 1);
    int slot = g_off[e] + pos;
    g_tok[slot] = t;
    g_slotw[slot] = g_tw[t*2+k];
    g_tokslot[t*2+k] = slot;
  }
}

// ---------------- activation: g_act = silu(g_act) * g_h3 ---------------------
__global__ __launch_bounds__(256) void act_kernel() {
  size_t i = ((size_t)blockIdx.x * 256 + threadIdx.x) * 4;
  float4 h1 = *(float4*)(g_act + i);
  float4 h3 = *(const float4*)(g_h3 + i);
  h1.x = h1.x / (1.f + __expf(-h1.x)) * h3.x;
  h1.y = h1.y / (1.f + __expf(-h1.y)) * h3.y;
  h1.z = h1.z / (1.f + __expf(-h1.z)) * h3.z;
  h1.w = h1.w / (1.f + __expf(-h1.w)) * h3.w;
  *(float4*)(g_act + i) = h1;
}

// ---------------- combine ----------------------------------------------------
__global__ __launch_bounds__(256) void combine_kernel(float* __restrict__ outh) {
  int t = blockIdx.x;
  int s0 = g_tokslot[t*2], s1 = g_tokslot[t*2+1];
  int i = threadIdx.x * 4;
  float4 h  = *(float4*)(outh + (size_t)t * DD + i);
  float4 p0 = *(const float4*)(g_part + (size_t)s0 * DD + i);
  float4 p1 = *(const float4*)(g_part + (size_t)s1 * DD + i);
  h.x += p0.x + p1.x; h.y += p0.y + p1.y; h.z += p0.z + p1.z; h.w += p0.w + p1.w;
  *(float4*)(outh + (size_t)t * DD + i) = h;
}

// ---------------- launcher ---------------------------------------------------
extern "C" void kernel_launch(void* const* d_in, const int* in_sizes, int n_in,
                              void* d_out, int out_size) {
  const float* hidden = (const float*)d_in[0];
  const float* prev   = (const float*)d_in[2];
  const float* wq     = (const float*)d_in[3];
  const float* wk     = (const float*)d_in[4];
  const float* wv     = (const float*)d_in[5];
  const float* wo     = (const float*)d_in[6];
  const float* mixw   = (const float*)d_in[7];
  const float* mixb   = (const float*)d_in[8];
  const float* gatew  = (const float*)d_in[9];
  const float* w1     = (const float*)d_in[10];
  const float* w2     = (const float*)d_in[11];
  const float* w3     = (const float*)d_in[12];
  const float* ln1    = (const float*)d_in[13];
  const float* ln2    = (const float*)d_in[14];
  const float* compw  = (const float*)d_in[15];
  const float* compb  = (const float*)d_in[16];

  float* out_h     = (float*)d_out;
  float* out_mixed = out_h + (size_t)TT * DD;
  float* out_comp  = out_mixed + (size_t)TT * DD;

  void *pX, *pQ, *pK, *pV, *pAttn, *pAO, *pH2, *pAct, *pH3, *pPart;
  cudaGetSymbolAddress(&pX, g_X);
  cudaGetSymbolAddress(&pQ, g_Q);
  cudaGetSymbolAddress(&pK, g_K);
  cudaGetSymbolAddress(&pV, g_V);
  cudaGetSymbolAddress(&pAttn, g_attn);
  cudaGetSymbolAddress(&pAO, g_attnout);
  cudaGetSymbolAddress(&pH2, g_h2);
  cudaGetSymbolAddress(&pAct, g_act);
  cudaGetSymbolAddress(&pH3, g_h3);
  cudaGetSymbolAddress(&pPart, g_part);
  float* X = (float*)pX; float* Q = (float*)pQ; float* K = (float*)pK;
  float* V = (float*)pV; float* ATT = (float*)pAttn; float* AO = (float*)pAO;
  float* H2 = (float*)pH2; float* ACT = (float*)pAct; float* H3 = (float*)pH3;
  float* PART = (float*)pPart;

  rmsnorm_kernel<<<TT, 256>>>(hidden, ln1, X);
  // fused QKV: N=1536 (8 blocks Q, 2 K, 2 V)
  gemm_h<4><<<dim3(12, TT/128), 256>>>(
      X, nullptr, wq, wk, wv, nullptr, nullptr, Q, K, V, DD, DD);
  attn_kernel<<<dim3(SS/128, HH, BB), 128>>>();
  gemm_h<0><<<dim3(DD/128, TT/128), 256>>>(
      ATT, nullptr, wo, nullptr, nullptr, nullptr, nullptr, AO, nullptr, nullptr, DD, DD);
  gemm_h<1><<<dim3(DD/128, TT/128), 256>>>(
      AO, prev, mixw, nullptr, nullptr, mixb, hidden, out_mixed, out_h, nullptr, 2*DD, DD);
  rmsnorm_kernel<<<TT, 256>>>(out_h, ln2, H2);
  zero_kernel<<<1, 32>>>();
  gate_kernel<<<TT/8, 256>>>(gatew);
  scan_kernel<<<1, 32>>>();
  scatter_kernel<<<TT/256, 256>>>();
  gemm_h<2><<<dim3(FFF/128, TT/128, EE), 256>>>(
      H2, nullptr, w1, nullptr, nullptr, nullptr, nullptr, ACT, nullptr, nullptr, DD, FFF);
  gemm_h<2><<<dim3(FFF/128, TT/128, EE), 256>>>(
      H2, nullptr, w3, nullptr, nullptr, nullptr, nullptr, H3, nullptr, nullptr, DD, FFF);
  act_kernel<<<(int)(((size_t)NSLOT*FFF)/(256*4)), 256>>>();
  gemm_h<3><<<dim3(DD/128, TT/128, EE), 256>>>(
      ACT, nullptr, w2, nullptr, nullptr, nullptr, nullptr, PART, nullptr, nullptr, FFF, DD);
  combine_kernel<<<TT, 256>>>(out_h);
  gemm_h<0><<<dim3(CCOMP/128, TT/128), 256>>>(
      out_h, nullptr, compw, nullptr, nullptr, compb, nullptr, out_comp, nullptr, nullptr, DD, CCOMP);
}

// round 8
// speedup vs baseline: 1.7921x; 1.2219x over previous
#include <cuda_runtime.h>
#include <cuda_fp16.h>
#include <math.h>
#include <stdint.h>

#define BB 4
#define SS 1024
#define DD 1024
#define TT (BB*SS)           // 4096 tokens
#define HH 16
#define KVHH 4
#define HDD 64
#define EE 8
#define FFF 2816
#define CCOMP 256
#define NSLOT (TT*2)
#define NSTG 4

// A stage: 128 rows x 40 halves (32 data + 8 pad) = 10240 B
// B stage: 32 rows x 136 halves (128 data + 8 pad) = 8704 B
#define ASTGB (128*40*2)
#define BSTGB (32*136*2)
#define GSMEM (NSTG*(ASTGB+BSTGB))   // 75776 bytes dynamic smem

// ---------------- fp16 weights/activations (static device scratch) -----------
__device__ __half h_wq[DD*DD];
__device__ __half h_wk[DD*256];
__device__ __half h_wv[DD*256];
__device__ __half h_wo[DD*DD];
__device__ __half h_mixw[2*DD*DD];
__device__ __half h_w1[EE*DD*FFF];
__device__ __half h_w2[EE*FFF*DD];
__device__ __half h_w3[EE*DD*FFF];
__device__ __half h_compw[DD*CCOMP];
__device__ __half h_prev[TT*DD];

__device__ __half h_X[TT*DD];          // rmsnorm1 out
__device__ __half h_attn[TT*DD];       // attention out (pre-WO)
__device__ __half h_AO[TT*DD];         // after WO
__device__ __half h_h2[TT*DD];         // rmsnorm2 out
__device__ __half h_act[NSLOT*FFF];    // h1 then silu(h1)*h3
__device__ __half h_h3v[NSLOT*FFF];    // h3
__device__ __half h_outh[TT*DD];       // final h (comp GEMM input)

__device__ float g_Q[TT*DD];
__device__ float g_K[TT*KVHH*HDD];
__device__ float g_V[TT*KVHH*HDD];
__device__ float g_part[NSLOT*DD];
__device__ int   g_tok[NSLOT];
__device__ float g_slotw[NSLOT];
__device__ int   g_tokslot[TT*2];
__device__ int   g_te[TT*2];
__device__ float g_tw[TT*2];
__device__ int   g_cnt[EE];
__device__ int   g_off[EE+1];
__device__ int   g_cur[EE];

// ---------------- helpers -----------------------------------------------------
__device__ __forceinline__ void mma_f16(float c[4],
    uint32_t a0, uint32_t a1, uint32_t a2, uint32_t a3,
    uint32_t b0, uint32_t b1) {
  asm volatile(
    "mma.sync.aligned.m16n8k16.row.col.f32.f16.f16.f32 "
    "{%0,%1,%2,%3},{%4,%5,%6,%7},{%8,%9},{%0,%1,%2,%3};"
    : "+f"(c[0]), "+f"(c[1]), "+f"(c[2]), "+f"(c[3])
    : "r"(a0), "r"(a1), "r"(a2), "r"(a3), "r"(b0), "r"(b1));
}
__device__ __forceinline__ uint32_t smem_u32(const void* p) {
  return (uint32_t)__cvta_generic_to_shared(p);
}
__device__ __forceinline__ void cpa16(uint32_t s, const void* g) {
  asm volatile("cp.async.cg.shared.global [%0], [%1], 16;" :: "r"(s), "l"(g));
}
__device__ __forceinline__ void ldsm4(uint32_t r[4], uint32_t addr) {
  asm volatile("ldmatrix.sync.aligned.m8n8.x4.shared.b16 {%0,%1,%2,%3}, [%4];"
               : "=r"(r[0]), "=r"(r[1]), "=r"(r[2]), "=r"(r[3]) : "r"(addr));
}
__device__ __forceinline__ void ldsm4t(uint32_t r[4], uint32_t addr) {
  asm volatile("ldmatrix.sync.aligned.m8n8.x4.trans.shared.b16 {%0,%1,%2,%3}, [%4];"
               : "=r"(r[0]), "=r"(r[1]), "=r"(r[2]), "=r"(r[3]) : "r"(addr));
}

// ---------------- f32 -> f16 convert ------------------------------------------
__global__ __launch_bounds__(256) void f2h_kernel(
    const float* __restrict__ in, __half* __restrict__ out, int n) {
  int i = (blockIdx.x * 256 + threadIdx.x) * 4;
  if (i >= n) return;
  float4 v = *(const float4*)(in + i);
  __half2* o = (__half2*)(out + i);
  o[0] = __floats2half2_rn(v.x, v.y);
  o[1] = __floats2half2_rn(v.z, v.w);
}

// ---------------- FP16 GEMM: cp.async 4-stage + ldmatrix ----------------------
// Block 128x128, 256 thr = 8 warps (2 warpM x 4 warpN), warp 64x32, Kchunk 32.
// A smem [stg][128][40] halves (80B stride -> LDSM conflict-free, fills in-row).
// B smem [stg][32][136] halves (272B stride -> LDSM.T conflict-free).
// MODE 0: C=A@B(+bias), optional half CH    MODE 1: mix (A|A2; C=mixed, C2=h)
// MODE 2: MoE gathered rows -> half CH       MODE 3: MoE down -> fp32 C *slotw
// MODE 4: fused QKV (B/B2/B3 -> C/C2/C3 fp32)
template<int MODE>
__global__ __launch_bounds__(256, 2) void gemm_h(
    const __half* __restrict__ A, const __half* __restrict__ A2,
    const __half* __restrict__ B, const __half* __restrict__ B2,
    const __half* __restrict__ B3, const float* __restrict__ bias,
    const float* __restrict__ hidden, float* __restrict__ C,
    float* __restrict__ C2, float* __restrict__ C3,
    __half* __restrict__ CH, int K, int N) {
  extern __shared__ __align__(16) char dynsm[];
  uint32_t smA = smem_u32(dynsm);                    // NSTG stages of A
  uint32_t smB = smA + NSTG * ASTGB;                 // NSTG stages of B

  int base = 0, cnt = 0;
  if (MODE == 2 || MODE == 3) {
    int e = blockIdx.z;
    base = g_off[e];
    cnt = g_off[e+1] - base;
    if ((int)(blockIdx.y * 128) >= cnt) return;
    B += (size_t)e * K * N;
  }
  int rowBase = blockIdx.y * 128;
  int colBase = blockIdx.x * 128;
  int tid = threadIdx.x;
  int lane = tid & 31;
  int warp = tid >> 5;
  int warpM = warp & 1;
  int warpN = warp >> 1;

  const __half* Bsel = B;
  float* Csel = C;
  int bN = N, cOff = 0;
  if (MODE == 4) {
    if (colBase < DD)            { Bsel = B;  Csel = C;  bN = DD;  cOff = 0; }
    else if (colBase < DD + 256) { Bsel = B2; Csel = C2; bN = 256; cOff = DD; }
    else                         { Bsel = B3; Csel = C3; bN = 256; cOff = DD + 256; }
  }

  // ---- A fill: thread row am=tid>>1, 16 halves at aseg ∈ {0,16} ------------
  int am = tid >> 1;
  const __half* arow0 = nullptr;
  const __half* arow1 = nullptr;
  if (MODE == 0 || MODE == 4) {
    arow0 = A + (size_t)(rowBase + am) * K;
  } else if (MODE == 1) {
    arow0 = A  + (size_t)(rowBase + am) * DD;
    arow1 = A2 + (size_t)(rowBase + am) * DD;
  } else if (MODE == 2) {
    int rr = rowBase + am; if (rr > cnt - 1) rr = cnt - 1;
    arow0 = A + (size_t)g_tok[base + rr] * K;
  } else {
    int rr = rowBase + am; if (rr > cnt - 1) rr = cnt - 1;
    arow0 = A + (size_t)(base + rr) * K;
  }
  int aseg = (tid & 1) * 16;

  // ---- B fill: thread row brow=tid>>3, 16 halves at bseg -------------------
  int brow = tid >> 3;
  int bseg = (tid & 7) * 16;
  const __half* bptr = Bsel + (size_t)brow * bN + (colBase - cOff) + bseg;

  uint32_t aFill = smA + (uint32_t)((am * 40 + aseg) * 2);
  uint32_t bFill = smB + (uint32_t)((brow * 136 + bseg) * 2);

  auto issue = [&](int stg, int k0) {
    const __half* ap = arow0;
    int kk = k0;
    if (MODE == 1 && k0 >= DD) { ap = arow1; kk = k0 - DD; }
    cpa16(aFill + stg * ASTGB,      ap + kk + aseg);
    cpa16(aFill + stg * ASTGB + 16, ap + kk + aseg + 8);
    const __half* bp = bptr + (size_t)k0 * bN;
    cpa16(bFill + stg * BSTGB,      bp);
    cpa16(bFill + stg * BSTGB + 16, bp + 8);
  };

  // ---- ldmatrix lane bases -------------------------------------------------
  int l15 = lane & 15, lhi = lane >> 4;
  uint32_t aBase = smA + (uint32_t)(((warpM * 64 + l15) * 40 + lhi * 8) * 2);
  uint32_t bBase = smB + (uint32_t)((l15 * 136 + warpN * 32 + lhi * 8) * 2);

  float acc[4][4][4] = {};
  int nch = K / 32;

  issue(0, 0);  asm volatile("cp.async.commit_group;");
  issue(1, 32); asm volatile("cp.async.commit_group;");
  issue(2, 64); asm volatile("cp.async.commit_group;");

  for (int i = 0; i < nch; i++) {
    asm volatile("cp.async.wait_group 2;");
    __syncthreads();
    int nk = i + 3;
    if (nk < nch) issue(nk & 3, nk * 32);
    asm volatile("cp.async.commit_group;");

    int st = i & 3;
    uint32_t aStg = aBase + st * ASTGB;
    uint32_t bStg = bBase + st * BSTGB;
#pragma unroll
    for (int kc = 0; kc < 2; kc++) {
      uint32_t a[4][4];
#pragma unroll
      for (int mt = 0; mt < 4; mt++)
        ldsm4(a[mt], aStg + (uint32_t)((mt * 640 + kc * 16) * 2));   // 16 rows * 40
      uint32_t b[2][4];
#pragma unroll
      for (int nh = 0; nh < 2; nh++)
        ldsm4t(b[nh], bStg + (uint32_t)((kc * 2176 + nh * 16) * 2)); // 16 rows * 136
#pragma unroll
      for (int mt = 0; mt < 4; mt++)
#pragma unroll
        for (int nt = 0; nt < 4; nt++)
          mma_f16(acc[mt][nt], a[mt][0], a[mt][1], a[mt][2], a[mt][3],
                  b[nt >> 1][(nt & 1) * 2], b[nt >> 1][(nt & 1) * 2 + 1]);
    }
  }

  // ---- epilogue ----
  int kq = lane & 3;
  int mq = lane >> 2;
#pragma unroll
  for (int mt = 0; mt < 4; mt++) {
#pragma unroll
    for (int half = 0; half < 2; half++) {
      int r = rowBase + warpM * 64 + mt * 16 + mq + half * 8;
#pragma unroll
      for (int nt = 0; nt < 4; nt++) {
        int n = colBase + warpN * 32 + nt * 8 + 2 * kq;
        float v0 = acc[mt][nt][half * 2];
        float v1 = acc[mt][nt][half * 2 + 1];
        if (MODE == 0) {
          if (bias) { v0 += bias[n]; v1 += bias[n + 1]; }
          if (C)  *(float2*)(C + (size_t)r * N + n) = make_float2(v0, v1);
          if (CH) *(__half2*)(CH + (size_t)r * N + n) = __floats2half2_rn(v0, v1);
        } else if (MODE == 1) {
          v0 += bias[n]; v1 += bias[n + 1];
          *(float2*)(C + (size_t)r * N + n) = make_float2(v0, v1);
          float h0 = hidden[(size_t)r * N + n];
          float h1 = hidden[(size_t)r * N + n + 1];
          *(float2*)(C2 + (size_t)r * N + n) = make_float2(h0 + v0, h1 + v1);
        } else if (MODE == 2) {
          if (r < cnt)
            *(__half2*)(CH + (size_t)(base + r) * N + n) = __floats2half2_rn(v0, v1);
        } else if (MODE == 3) {
          if (r < cnt) {
            float w = g_slotw[base + r];
            *(float2*)(C + (size_t)(base + r) * N + n) = make_float2(w*v0, w*v1);
          }
        } else {  // MODE 4
          *(float2*)(Csel + (size_t)r * bN + (n - cOff)) = make_float2(v0, v1);
        }
      }
    }
  }
}

// ---------------- rmsnorm (fp32 in -> fp16 out) -------------------------------
__global__ __launch_bounds__(256) void rmsnorm_kernel(
    const float* __restrict__ x, const float* __restrict__ w, __half* __restrict__ out) {
  int row = blockIdx.x;
  const float* xr = x + (size_t)row * DD;
  float ss = 0.f;
  for (int i = threadIdx.x; i < DD; i += 256) { float v = xr[i]; ss += v * v; }
  __shared__ float red[8];
#pragma unroll
  for (int o = 16; o; o >>= 1) ss += __shfl_xor_sync(0xffffffffu, ss, o);
  if ((threadIdx.x & 31) == 0) red[threadIdx.x >> 5] = ss;
  __syncthreads();
  if (threadIdx.x < 8) {
    float v = red[threadIdx.x];
#pragma unroll
    for (int o = 4; o; o >>= 1) v += __shfl_xor_sync(0xffu, v, o);
    if (threadIdx.x == 0) red[0] = rsqrtf(v / (float)DD + 1e-6f);
  }
  __syncthreads();
  float r = red[0];
  for (int i = threadIdx.x; i < DD; i += 256)
    out[(size_t)row * DD + i] = __float2half_rn(w[i] * (xr[i] * r));
}

// ---------------- attention (fp32 math; fp16 output) --------------------------
__global__ __launch_bounds__(128) void attn_kernel() {
  int q = blockIdx.x * 128 + threadIdx.x;
  int h = blockIdx.y;
  int b = blockIdx.z;
  int t = b * SS + q;
  int kv = h / (HH / KVHH);
  const float* qp = g_Q + (size_t)t * DD + h * HDD;
  float qr[HDD];
#pragma unroll
  for (int i = 0; i < HDD; i++) qr[i] = qp[i] * 0.125f;
  float acc[HDD] = {};
  float m = -1e30f, l = 0.f;
  __shared__ float Ks[32][HDD];
  __shared__ float Vs[32][HDD];
  int lr = threadIdx.x >> 2;
  int lc = (threadIdx.x & 3) * 16;
  for (int kt = 0; kt < SS; kt += 32) {
    const float* kp = g_K + (size_t)(b*SS + kt + lr) * (KVHH*HDD) + kv*HDD + lc;
    const float* vp = g_V + (size_t)(b*SS + kt + lr) * (KVHH*HDD) + kv*HDD + lc;
#pragma unroll
    for (int i = 0; i < 4; i++) {
      *(float4*)&Ks[lr][lc + i*4] = *(const float4*)(kp + i*4);
      *(float4*)&Vs[lr][lc + i*4] = *(const float4*)(vp + i*4);
    }
    __syncthreads();
    float sc[32];
#pragma unroll
    for (int j = 0; j < 32; j++) {
      float s = 0.f;
#pragma unroll
      for (int i = 0; i < HDD/4; i++) {
        float4 k4 = *(const float4*)&Ks[j][i*4];
        s += qr[i*4]*k4.x + qr[i*4+1]*k4.y + qr[i*4+2]*k4.z + qr[i*4+3]*k4.w;
      }
      sc[j] = s;
    }
    float mt = m;
#pragma unroll
    for (int j = 0; j < 32; j++) mt = fmaxf(mt, sc[j]);
    float corr = __expf(m - mt);
    m = mt;
    l *= corr;
#pragma unroll
    for (int i = 0; i < HDD; i++) acc[i] *= corr;
#pragma unroll
    for (int j = 0; j < 32; j++) {
      float p = __expf(sc[j] - m);
      l += p;
#pragma unroll
      for (int i = 0; i < HDD/4; i++) {
        float4 v4 = *(const float4*)&Vs[j][i*4];
        acc[i*4]   += p * v4.x;
        acc[i*4+1] += p * v4.y;
        acc[i*4+2] += p * v4.z;
        acc[i*4+3] += p * v4.w;
      }
    }
    __syncthreads();
  }
  float inv = 1.f / l;
  __half* op = h_attn + (size_t)t * DD + h * HDD;
#pragma unroll
  for (int i = 0; i < HDD; i++) op[i] = __float2half_rn(acc[i] * inv);
}

// ---------------- MoE routing ------------------------------------------------
__global__ void zero_kernel() { if (threadIdx.x < EE) g_cnt[threadIdx.x] = 0; }

__global__ __launch_bounds__(256) void gate_kernel(const float* __restrict__ gw) {
  int warp = (blockIdx.x * 256 + threadIdx.x) >> 5;
  int lane = threadIdx.x & 31;
  if (warp >= TT) return;
  const __half* x = h_h2 + (size_t)warp * DD;
  float acc[EE] = {};
  for (int k = lane; k < DD; k += 32) {
    float xv = __half2float(x[k]);
    const float* g = gw + (size_t)k * EE;
#pragma unroll
    for (int e = 0; e < EE; e++) acc[e] += xv * g[e];
  }
#pragma unroll
  for (int e = 0; e < EE; e++)
#pragma unroll
    for (int o = 16; o; o >>= 1) acc[e] += __shfl_xor_sync(0xffffffffu, acc[e], o);
  if (lane == 0) {
    float mx = acc[0];
#pragma unroll
    for (int e = 1; e < EE; e++) mx = fmaxf(mx, acc[e]);
    float p[EE];
#pragma unroll
    for (int e = 0; e < EE; e++) p[e] = __expf(acc[e] - mx);
    int i0 = 0;
#pragma unroll
    for (int e = 1; e < EE; e++) if (p[e] > p[i0]) i0 = e;
    int i1 = (i0 == 0) ? 1 : 0;
#pragma unroll
    for (int e = 0; e < EE; e++) if (e != i0 && p[e] > p[i1]) i1 = e;
    float w0 = p[i0], w1 = p[i1];
    float inv = 1.f / (w0 + w1);
    w0 *= inv; w1 *= inv;
    g_te[warp*2] = i0; g_te[warp*2+1] = i1;
    g_tw[warp*2] = w0; g_tw[warp*2+1] = w1;
    atomicAdd(&g_cnt[i0], 1);
    atomicAdd(&g_cnt[i1], 1);
  }
}

__global__ void scan_kernel() {
  if (threadIdx.x == 0) {
    int o = 0;
    for (int e = 0; e < EE; e++) { g_off[e] = o; o += g_cnt[e]; g_cur[e] = 0; }
    g_off[EE] = o;
  }
}

__global__ __launch_bounds__(256) void scatter_kernel() {
  int t = blockIdx.x * 256 + threadIdx.x;
  if (t >= TT) return;
#pragma unroll
  for (int k = 0; k < 2; k++) {
    int e = g_te[t*2+k];
    int pos = atomicAdd(&g_cur[e], 1);
    int slot = g_off[e] + pos;
    g_tok[slot] = t;
    g_slotw[slot] = g_tw[t*2+k];
    g_tokslot[t*2+k] = slot;
  }
}

// ---------------- activation: h_act = silu(h_act) * h_h3v (fp32 math) ---------
__global__ __launch_bounds__(256) void act_kernel() {
  size_t i = ((size_t)blockIdx.x * 256 + threadIdx.x) * 8;
  __half2* a = (__half2*)(h_act + i);
  const __half2* h = (const __half2*)(h_h3v + i);
#pragma unroll
  for (int j = 0; j < 4; j++) {
    float2 h1 = __half22float2(a[j]);
    float2 h3 = __half22float2(h[j]);
    h1.x = h1.x / (1.f + __expf(-h1.x)) * h3.x;
    h1.y = h1.y / (1.f + __expf(-h1.y)) * h3.y;
    a[j] = __floats2half2_rn(h1.x, h1.y);
  }
}

// ---------------- combine: outh += part0+part1; also fp16 copy ---------------
__global__ __launch_bounds__(256) void combine_kernel(float* __restrict__ outh) {
  int t = blockIdx.x;
  int s0 = g_tokslot[t*2], s1 = g_tokslot[t*2+1];
  int i = threadIdx.x * 4;
  float4 h  = *(float4*)(outh + (size_t)t * DD + i);
  float4 p0 = *(const float4*)(g_part + (size_t)s0 * DD + i);
  float4 p1 = *(const float4*)(g_part + (size_t)s1 * DD + i);
  h.x += p0.x + p1.x; h.y += p0.y + p1.y; h.z += p0.z + p1.z; h.w += p0.w + p1.w;
  *(float4*)(outh + (size_t)t * DD + i) = h;
  __half2* o = (__half2*)(h_outh + (size_t)t * DD + i);
  o[0] = __floats2half2_rn(h.x, h.y);
  o[1] = __floats2half2_rn(h.z, h.w);
}

// ---------------- launcher ---------------------------------------------------
static inline int cvgrid(int n) { return (n / 4 + 255) / 256; }

extern "C" void kernel_launch(void* const* d_in, const int* in_sizes, int n_in,
                              void* d_out, int out_size) {
  const float* hidden = (const float*)d_in[0];
  const float* prev   = (const float*)d_in[2];
  const float* wq     = (const float*)d_in[3];
  const float* wk     = (const float*)d_in[4];
  const float* wv     = (const float*)d_in[5];
  const float* wo     = (const float*)d_in[6];
  const float* mixw   = (const float*)d_in[7];
  const float* mixb   = (const float*)d_in[8];
  const float* gatew  = (const float*)d_in[9];
  const float* w1     = (const float*)d_in[10];
  const float* w2     = (const float*)d_in[11];
  const float* w3     = (const float*)d_in[12];
  const float* ln1    = (const float*)d_in[13];
  const float* ln2    = (const float*)d_in[14];
  const float* compw  = (const float*)d_in[15];
  const float* compb  = (const float*)d_in[16];

  float* out_h     = (float*)d_out;
  float* out_mixed = out_h + (size_t)TT * DD;
  float* out_comp  = out_mixed + (size_t)TT * DD;

  void *pwq,*pwk,*pwv,*pwo,*pmix,*pw1,*pw2,*pw3,*pcw,*pprev;
  void *pX,*pAT,*pAO,*pH2,*pACT,*pH3,*pOH,*pQ,*pK,*pV,*pPart;
  cudaGetSymbolAddress(&pwq, h_wq);   cudaGetSymbolAddress(&pwk, h_wk);
  cudaGetSymbolAddress(&pwv, h_wv);   cudaGetSymbolAddress(&pwo, h_wo);
  cudaGetSymbolAddress(&pmix, h_mixw);cudaGetSymbolAddress(&pw1, h_w1);
  cudaGetSymbolAddress(&pw2, h_w2);   cudaGetSymbolAddress(&pw3, h_w3);
  cudaGetSymbolAddress(&pcw, h_compw);cudaGetSymbolAddress(&pprev, h_prev);
  cudaGetSymbolAddress(&pX, h_X);     cudaGetSymbolAddress(&pAT, h_attn);
  cudaGetSymbolAddress(&pAO, h_AO);   cudaGetSymbolAddress(&pH2, h_h2);
  cudaGetSymbolAddress(&pACT, h_act); cudaGetSymbolAddress(&pH3, h_h3v);
  cudaGetSymbolAddress(&pOH, h_outh); cudaGetSymbolAddress(&pQ, g_Q);
  cudaGetSymbolAddress(&pK, g_K);     cudaGetSymbolAddress(&pV, g_V);
  cudaGetSymbolAddress(&pPart, g_part);
  __half *HWQ=(__half*)pwq, *HWK=(__half*)pwk, *HWV=(__half*)pwv, *HWO=(__half*)pwo;
  __half *HMIX=(__half*)pmix, *HW1=(__half*)pw1, *HW2=(__half*)pw2, *HW3=(__half*)pw3;
  __half *HCW=(__half*)pcw, *HPREV=(__half*)pprev;
  __half *HX=(__half*)pX, *HAT=(__half*)pAT, *HAO=(__half*)pAO, *HH2=(__half*)pH2;
  __half *HACT=(__half*)pACT, *HH3=(__half*)pH3, *HOH=(__half*)pOH;
  float *Q=(float*)pQ, *K=(float*)pK, *V=(float*)pV, *PART=(float*)pPart;

  cudaFuncSetAttribute(gemm_h<0>, cudaFuncAttributeMaxDynamicSharedMemorySize, GSMEM);
  cudaFuncSetAttribute(gemm_h<1>, cudaFuncAttributeMaxDynamicSharedMemorySize, GSMEM);
  cudaFuncSetAttribute(gemm_h<2>, cudaFuncAttributeMaxDynamicSharedMemorySize, GSMEM);
  cudaFuncSetAttribute(gemm_h<3>, cudaFuncAttributeMaxDynamicSharedMemorySize, GSMEM);
  cudaFuncSetAttribute(gemm_h<4>, cudaFuncAttributeMaxDynamicSharedMemorySize, GSMEM);

  // ---- one-time (per launch) fp32 -> fp16 conversions ----
  f2h_kernel<<<cvgrid(DD*DD), 256>>>(wq, HWQ, DD*DD);
  f2h_kernel<<<cvgrid(DD*256), 256>>>(wk, HWK, DD*256);
  f2h_kernel<<<cvgrid(DD*256), 256>>>(wv, HWV, DD*256);
  f2h_kernel<<<cvgrid(DD*DD), 256>>>(wo, HWO, DD*DD);
  f2h_kernel<<<cvgrid(2*DD*DD), 256>>>(mixw, HMIX, 2*DD*DD);
  f2h_kernel<<<cvgrid(EE*DD*FFF), 256>>>(w1, HW1, EE*DD*FFF);
  f2h_kernel<<<cvgrid(EE*FFF*DD), 256>>>(w2, HW2, EE*FFF*DD);
  f2h_kernel<<<cvgrid(EE*DD*FFF), 256>>>(w3, HW3, EE*DD*FFF);
  f2h_kernel<<<cvgrid(DD*CCOMP), 256>>>(compw, HCW, DD*CCOMP);
  f2h_kernel<<<cvgrid(TT*DD), 256>>>(prev, HPREV, TT*DD);

  // ---- pipeline ----
  rmsnorm_kernel<<<TT, 256>>>(hidden, ln1, HX);
  gemm_h<4><<<dim3(12, TT/128), 256, GSMEM>>>(
      HX, nullptr, HWQ, HWK, HWV, nullptr, nullptr, Q, K, V, nullptr, DD, DD);
  attn_kernel<<<dim3(SS/128, HH, BB), 128>>>();
  gemm_h<0><<<dim3(DD/128, TT/128), 256, GSMEM>>>(
      HAT, nullptr, HWO, nullptr, nullptr, nullptr, nullptr,
      nullptr, nullptr, nullptr, HAO, DD, DD);
  gemm_h<1><<<dim3(DD/128, TT/128), 256, GSMEM>>>(
      HAO, HPREV, HMIX, nullptr, nullptr, mixb, hidden,
      out_mixed, out_h, nullptr, nullptr, 2*DD, DD);
  rmsnorm_kernel<<<TT, 256>>>(out_h, ln2, HH2);
  zero_kernel<<<1, 32>>>();
  gate_kernel<<<TT/8, 256>>>(gatew);
  scan_kernel<<<1, 32>>>();
  scatter_kernel<<<TT/256, 256>>>();
  gemm_h<2><<<dim3(FFF/128, TT/128, EE), 256, GSMEM>>>(
      HH2, nullptr, HW1, nullptr, nullptr, nullptr, nullptr,
      nullptr, nullptr, nullptr, HACT, DD, FFF);
  gemm_h<2><<<dim3(FFF/128, TT/128, EE), 256, GSMEM>>>(
      HH2, nullptr, HW3, nullptr, nullptr, nullptr, nullptr,
      nullptr, nullptr, nullptr, HH3, DD, FFF);
  act_kernel<<<(int)(((size_t)NSLOT*FFF)/(256*8)), 256>>>();
  gemm_h<3><<<dim3(DD/128, TT/128, EE), 256, GSMEM>>>(
      HACT, nullptr, HW2, nullptr, nullptr, nullptr, nullptr,
      PART, nullptr, nullptr, nullptr, FFF, DD);
  combine_kernel<<<TT, 256>>>(out_h);
  gemm_h<0><<<dim3(CCOMP/128, TT/128), 256, GSMEM>>>(
      HOH, nullptr, HCW, nullptr, nullptr, compb, nullptr,
      out_comp, nullptr, nullptr, nullptr, DD, CCOMP);
}

// round 10
// speedup vs baseline: 2.8621x; 1.5971x over previous
#include <cuda_runtime.h>
#include <cuda_fp16.h>
#include <math.h>
#include <stdint.h>

#define BB 4
#define SS 1024
#define DD 1024
#define TT (BB*SS)           // 4096 tokens
#define HH 16
#define KVHH 4
#define HDD 64
#define EE 8
#define FFF 2816
#define CCOMP 256
#define NSLOT (TT*2)
#define NSTG 4

// GEMM stages
#define ASTGB (128*40*2)
#define BSTGB (32*136*2)
#define GSMEM (NSTG*(ASTGB+BSTGB))   // 75776 bytes dynamic smem

// attention tile geometry
#define ATP 72                        // padded row stride (halves)

// ---------------- fp16 weights/activations (static device scratch) -----------
__device__ __half h_wq[DD*DD];
__device__ __half h_wk[DD*256];
__device__ __half h_wv[DD*256];
__device__ __half h_wo[DD*DD];
__device__ __half h_mixw[2*DD*DD];
__device__ __half h_w1[EE*DD*FFF];
__device__ __half h_w2[EE*FFF*DD];
__device__ __half h_w3[EE*DD*FFF];
__device__ __half h_compw[DD*CCOMP];
__device__ __half h_prev[TT*DD];

__device__ __half h_X[TT*DD];          // rmsnorm1 out
__device__ __half h_Qh[TT*DD];         // fp16 Q
__device__ __half h_Kh[TT*256];        // fp16 K
__device__ __half h_Vh[TT*256];        // fp16 V
__device__ __half h_attn[TT*DD];       // attention out (pre-WO)
__device__ __half h_AO[TT*DD];         // after WO
__device__ __half h_h2[TT*DD];         // rmsnorm2 out
__device__ __half h_act[NSLOT*FFF];    // h1 then silu(h1)*h3
__device__ __half h_h3v[NSLOT*FFF];    // h3
__device__ __half h_outh[TT*DD];       // final h (comp GEMM input)

__device__ float g_part[NSLOT*DD];
__device__ int   g_tok[NSLOT];
__device__ float g_slotw[NSLOT];
__device__ int   g_tokslot[TT*2];
__device__ int   g_te[TT*2];
__device__ float g_tw[TT*2];
__device__ int   g_cnt[EE];
__device__ int   g_off[EE+1];
__device__ int   g_cur[EE];

// ---------------- helpers -----------------------------------------------------
__device__ __forceinline__ void mma_f16(float c[4],
    uint32_t a0, uint32_t a1, uint32_t a2, uint32_t a3,
    uint32_t b0, uint32_t b1) {
  asm volatile(
    "mma.sync.aligned.m16n8k16.row.col.f32.f16.f16.f32 "
    "{%0,%1,%2,%3},{%4,%5,%6,%7},{%8,%9},{%0,%1,%2,%3};"
    : "+f"(c[0]), "+f"(c[1]), "+f"(c[2]), "+f"(c[3])
    : "r"(a0), "r"(a1), "r"(a2), "r"(a3), "r"(b0), "r"(b1));
}
__device__ __forceinline__ uint32_t smem_u32(const void* p) {
  return (uint32_t)__cvta_generic_to_shared(p);
}
__device__ __forceinline__ void cpa16(uint32_t s, const void* g) {
  asm volatile("cp.async.cg.shared.global [%0], [%1], 16;" :: "r"(s), "l"(g));
}
__device__ __forceinline__ void ldsm4(uint32_t r[4], uint32_t addr) {
  asm volatile("ldmatrix.sync.aligned.m8n8.x4.shared.b16 {%0,%1,%2,%3}, [%4];"
               : "=r"(r[0]), "=r"(r[1]), "=r"(r[2]), "=r"(r[3]) : "r"(addr));
}
__device__ __forceinline__ void ldsm4t(uint32_t r[4], uint32_t addr) {
  asm volatile("ldmatrix.sync.aligned.m8n8.x4.trans.shared.b16 {%0,%1,%2,%3}, [%4];"
               : "=r"(r[0]), "=r"(r[1]), "=r"(r[2]), "=r"(r[3]) : "r"(addr));
}
__device__ __forceinline__ uint32_t f2h2u(float lo, float hi) {
  __half2 h = __floats2half2_rn(lo, hi);
  return *(uint32_t*)&h;
}

// ---------------- f32 -> f16 convert ------------------------------------------
__global__ __launch_bounds__(256) void f2h_kernel(
    const float* __restrict__ in, __half* __restrict__ out, int n) {
  int i = (blockIdx.x * 256 + threadIdx.x) * 4;
  if (i >= n) return;
  float4 v = *(const float4*)(in + i);
  __half2* o = (__half2*)(out + i);
  o[0] = __floats2half2_rn(v.x, v.y);
  o[1] = __floats2half2_rn(v.z, v.w);
}

// ---------------- FP16 GEMM: cp.async 4-stage + ldmatrix ----------------------
// Block 128x128, 8 warps, warp 64x32, Kchunk 32.
// MODE 0: C=A@B(+bias), opt half CH   MODE 1: mix (A|A2; C=mixed, C2=h)
// MODE 2: MoE gathered -> half CH      MODE 3: MoE down -> fp32 C *slotw
// MODE 4: fused QKV -> HALF outputs (C/C2/C3 are __half* in disguise)
template<int MODE>
__global__ __launch_bounds__(256, 2) void gemm_h(
    const __half* __restrict__ A, const __half* __restrict__ A2,
    const __half* __restrict__ B, const __half* __restrict__ B2,
    const __half* __restrict__ B3, const float* __restrict__ bias,
    const float* __restrict__ hidden, float* __restrict__ C,
    float* __restrict__ C2, float* __restrict__ C3,
    __half* __restrict__ CH, int K, int N) {
  extern __shared__ __align__(16) char dynsm[];
  uint32_t smA = smem_u32(dynsm);
  uint32_t smB = smA + NSTG * ASTGB;

  int base = 0, cnt = 0;
  if (MODE == 2 || MODE == 3) {
    int e = blockIdx.z;
    base = g_off[e];
    cnt = g_off[e+1] - base;
    if ((int)(blockIdx.y * 128) >= cnt) return;
    B += (size_t)e * K * N;
  }
  int rowBase = blockIdx.y * 128;
  int colBase = blockIdx.x * 128;
  int tid = threadIdx.x;
  int lane = tid & 31;
  int warp = tid >> 5;
  int warpM = warp & 1;
  int warpN = warp >> 1;

  const __half* Bsel = B;
  float* Csel = C;
  int bN = N, cOff = 0;
  if (MODE == 4) {
    if (colBase < DD)            { Bsel = B;  Csel = C;  bN = DD;  cOff = 0; }
    else if (colBase < DD + 256) { Bsel = B2; Csel = C2; bN = 256; cOff = DD; }
    else                         { Bsel = B3; Csel = C3; bN = 256; cOff = DD + 256; }
  }

  int am = tid >> 1;
  const __half* arow0 = nullptr;
  const __half* arow1 = nullptr;
  if (MODE == 0 || MODE == 4) {
    arow0 = A + (size_t)(rowBase + am) * K;
  } else if (MODE == 1) {
    arow0 = A  + (size_t)(rowBase + am) * DD;
    arow1 = A2 + (size_t)(rowBase + am) * DD;
  } else if (MODE == 2) {
    int rr = rowBase + am; if (rr > cnt - 1) rr = cnt - 1;
    arow0 = A + (size_t)g_tok[base + rr] * K;
  } else {
    int rr = rowBase + am; if (rr > cnt - 1) rr = cnt - 1;
    arow0 = A + (size_t)(base + rr) * K;
  }
  int aseg = (tid & 1) * 16;

  int brow = tid >> 3;
  int bseg = (tid & 7) * 16;
  const __half* bptr = Bsel + (size_t)brow * bN + (colBase - cOff) + bseg;

  uint32_t aFill = smA + (uint32_t)((am * 40 + aseg) * 2);
  uint32_t bFill = smB + (uint32_t)((brow * 136 + bseg) * 2);

  auto issue = [&](int stg, int k0) {
    const __half* ap = arow0;
    int kk = k0;
    if (MODE == 1 && k0 >= DD) { ap = arow1; kk = k0 - DD; }
    cpa16(aFill + stg * ASTGB,      ap + kk + aseg);
    cpa16(aFill + stg * ASTGB + 16, ap + kk + aseg + 8);
    const __half* bp = bptr + (size_t)k0 * bN;
    cpa16(bFill + stg * BSTGB,      bp);
    cpa16(bFill + stg * BSTGB + 16, bp + 8);
  };

  int l15 = lane & 15, lhi = lane >> 4;
  uint32_t aBase = smA + (uint32_t)(((warpM * 64 + l15) * 40 + lhi * 8) * 2);
  uint32_t bBase = smB + (uint32_t)((l15 * 136 + warpN * 32 + lhi * 8) * 2);

  float acc[4][4][4] = {};
  int nch = K / 32;

  issue(0, 0);  asm volatile("cp.async.commit_group;");
  issue(1, 32); asm volatile("cp.async.commit_group;");
  issue(2, 64); asm volatile("cp.async.commit_group;");

  for (int i = 0; i < nch; i++) {
    asm volatile("cp.async.wait_group 2;");
    __syncthreads();
    int nk = i + 3;
    if (nk < nch) issue(nk & 3, nk * 32);
    asm volatile("cp.async.commit_group;");

    int st = i & 3;
    uint32_t aStg = aBase + st * ASTGB;
    uint32_t bStg = bBase + st * BSTGB;
#pragma unroll
    for (int kc = 0; kc < 2; kc++) {
      uint32_t a[4][4];
#pragma unroll
      for (int mt = 0; mt < 4; mt++)
        ldsm4(a[mt], aStg + (uint32_t)((mt * 640 + kc * 16) * 2));
      uint32_t b[2][4];
#pragma unroll
      for (int nh = 0; nh < 2; nh++)
        ldsm4t(b[nh], bStg + (uint32_t)((kc * 2176 + nh * 16) * 2));
#pragma unroll
      for (int mt = 0; mt < 4; mt++)
#pragma unroll
        for (int nt = 0; nt < 4; nt++)
          mma_f16(acc[mt][nt], a[mt][0], a[mt][1], a[mt][2], a[mt][3],
                  b[nt >> 1][(nt & 1) * 2], b[nt >> 1][(nt & 1) * 2 + 1]);
    }
  }

  int kq = lane & 3;
  int mq = lane >> 2;
#pragma unroll
  for (int mt = 0; mt < 4; mt++) {
#pragma unroll
    for (int half = 0; half < 2; half++) {
      int r = rowBase + warpM * 64 + mt * 16 + mq + half * 8;
#pragma unroll
      for (int nt = 0; nt < 4; nt++) {
        int n = colBase + warpN * 32 + nt * 8 + 2 * kq;
        float v0 = acc[mt][nt][half * 2];
        float v1 = acc[mt][nt][half * 2 + 1];
        if (MODE == 0) {
          if (bias) { v0 += bias[n]; v1 += bias[n + 1]; }
          if (C)  *(float2*)(C + (size_t)r * N + n) = make_float2(v0, v1);
          if (CH) *(__half2*)(CH + (size_t)r * N + n) = __floats2half2_rn(v0, v1);
        } else if (MODE == 1) {
          v0 += bias[n]; v1 += bias[n + 1];
          *(float2*)(C + (size_t)r * N + n) = make_float2(v0, v1);
          float h0 = hidden[(size_t)r * N + n];
          float h1 = hidden[(size_t)r * N + n + 1];
          *(float2*)(C2 + (size_t)r * N + n) = make_float2(h0 + v0, h1 + v1);
        } else if (MODE == 2) {
          if (r < cnt)
            *(__half2*)(CH + (size_t)(base + r) * N + n) = __floats2half2_rn(v0, v1);
        } else if (MODE == 3) {
          if (r < cnt) {
            float w = g_slotw[base + r];
            *(float2*)(C + (size_t)(base + r) * N + n) = make_float2(w*v0, w*v1);
          }
        } else {  // MODE 4: half outputs
          *(__half2*)((__half*)Csel + (size_t)r * bN + (n - cOff)) =
              __floats2half2_rn(v0, v1);
        }
      }
    }
  }
}

// ---------------- rmsnorm (fp32 in -> fp16 out) -------------------------------
__global__ __launch_bounds__(256) void rmsnorm_kernel(
    const float* __restrict__ x, const float* __restrict__ w, __half* __restrict__ out) {
  int row = blockIdx.x;
  const float* xr = x + (size_t)row * DD;
  float ss = 0.f;
  for (int i = threadIdx.x; i < DD; i += 256) { float v = xr[i]; ss += v * v; }
  __shared__ float red[8];
#pragma unroll
  for (int o = 16; o; o >>= 1) ss += __shfl_xor_sync(0xffffffffu, ss, o);
  if ((threadIdx.x & 31) == 0) red[threadIdx.x >> 5] = ss;
  __syncthreads();
  if (threadIdx.x < 8) {
    float v = red[threadIdx.x];
#pragma unroll
    for (int o = 4; o; o >>= 1) v += __shfl_xor_sync(0xffu, v, o);
    if (threadIdx.x == 0) red[0] = rsqrtf(v / (float)DD + 1e-6f);
  }
  __syncthreads();
  float r = red[0];
  for (int i = threadIdx.x; i < DD; i += 256)
    out[(size_t)row * DD + i] = __float2half_rn(w[i] * (xr[i] * r));
}

// ---------------- tensor-core flash attention ---------------------------------
// grid (SS/64, HH, BB), 128 threads = 4 warps; warp = 16 query rows.
// S = Q K^T via mma (Q ldsm4 A-op, K ldsm4 B-op on [key][hd]); softmax fp32;
// P fp16 via C->A fragment reuse; O += P V via ldsm4t on V[key][hd].
__global__ __launch_bounds__(128) void attn_tc_kernel() {
  __shared__ __align__(16) __half Qs[64][ATP];
  __shared__ __align__(16) __half Ks[2][64][ATP];
  __shared__ __align__(16) __half Vs[2][64][ATP];
  const int KVSTG = 64 * ATP * 2;   // bytes

  int h = blockIdx.y, b = blockIdx.z;
  int qBlock = blockIdx.x * 64;
  int kv = h >> 2;                  // H/KVH = 4
  int tid = threadIdx.x, lane = tid & 31, warp = tid >> 5;
  int qWarp = warp * 16;

  uint32_t sQ = smem_u32(&Qs[0][0]);
  uint32_t sK = smem_u32(&Ks[0][0][0]);
  uint32_t sV = smem_u32(&Vs[0][0][0]);

  int frow = tid >> 1;              // 0..63
  int fcol = (tid & 1) * 32;        // halves
  uint32_t qFill = sQ + (uint32_t)((frow * ATP + fcol) * 2);
  const __half* qsrc = h_Qh + (size_t)(b*SS + qBlock + frow) * DD + h * HDD + fcol;
#pragma unroll
  for (int j = 0; j < 4; j++) cpa16(qFill + j * 16, qsrc + j * 8);

  auto issueKV = [&](int stg, int tile) {
    const __half* ks = h_Kh + (size_t)(b*SS + tile*64 + frow) * 256 + kv * HDD + fcol;
    const __half* vs = h_Vh + (size_t)(b*SS + tile*64 + frow) * 256 + kv * HDD + fcol;
    uint32_t kf = sK + stg * KVSTG + (uint32_t)((frow * ATP + fcol) * 2);
    uint32_t vf = sV + stg * KVSTG + (uint32_t)((frow * ATP + fcol) * 2);
#pragma unroll
    for (int j = 0; j < 4; j++) {
      cpa16(kf + j * 16, ks + j * 8);
      cpa16(vf + j * 16, vs + j * 8);
    }
  };

  issueKV(0, 0);
  asm volatile("cp.async.commit_group;");

  int l15 = lane & 15, lhi = lane >> 4;
  int mq = lane >> 2, kq = lane & 3;
  uint32_t qfr[4][4];

  float m0 = -1e30f, m1 = -1e30f, l0 = 0.f, l1 = 0.f;
  float o[8][4] = {};

  const int NT = SS / 64;  // 16 key tiles
  for (int tile = 0; tile < NT; tile++) {
    if (tile + 1 < NT) issueKV((tile + 1) & 1, tile + 1);
    asm volatile("cp.async.commit_group;");
    if (tile + 1 < NT) { asm volatile("cp.async.wait_group 1;"); }
    else               { asm volatile("cp.async.wait_group 0;"); }
    __syncthreads();
    if (tile == 0) {
      uint32_t qAddr = sQ + (uint32_t)(((qWarp + l15) * ATP + lhi * 8) * 2);
#pragma unroll
      for (int kc = 0; kc < 4; kc++) ldsm4(qfr[kc], qAddr + kc * 32);
    }

    int st = tile & 1;
    // ---- S = Q K^T ----
    float s[8][4] = {};
    uint32_t kBase = sK + st * KVSTG;
#pragma unroll
    for (int kg = 0; kg < 4; kg++) {      // key groups of 16
      uint32_t ka = kBase + (uint32_t)(((kg * 16 + l15) * ATP + lhi * 8) * 2);
#pragma unroll
      for (int kc = 0; kc < 4; kc++) {    // hd chunks of 16
        uint32_t kb[4];
        ldsm4(kb, ka + kc * 32);
        mma_f16(s[kg*2],   qfr[kc][0], qfr[kc][1], qfr[kc][2], qfr[kc][3], kb[0], kb[2]);
        mma_f16(s[kg*2+1], qfr[kc][0], qfr[kc][1], qfr[kc][2], qfr[kc][3], kb[1], kb[3]);
      }
    }
    // ---- softmax update (scale 1/8) ----
    float mn0 = m0, mn1 = m1;
#pragma unroll
    for (int nt = 0; nt < 8; nt++) {
#pragma unroll
      for (int j = 0; j < 4; j++) s[nt][j] *= 0.125f;
      mn0 = fmaxf(mn0, fmaxf(s[nt][0], s[nt][1]));
      mn1 = fmaxf(mn1, fmaxf(s[nt][2], s[nt][3]));
    }
    mn0 = fmaxf(mn0, __shfl_xor_sync(0xffffffffu, mn0, 1));
    mn0 = fmaxf(mn0, __shfl_xor_sync(0xffffffffu, mn0, 2));
    mn1 = fmaxf(mn1, __shfl_xor_sync(0xffffffffu, mn1, 1));
    mn1 = fmaxf(mn1, __shfl_xor_sync(0xffffffffu, mn1, 2));
    float c0 = __expf(m0 - mn0), c1 = __expf(m1 - mn1);
    m0 = mn0; m1 = mn1;
    l0 *= c0; l1 *= c1;
#pragma unroll
    for (int nt = 0; nt < 8; nt++) {
      o[nt][0] *= c0; o[nt][1] *= c0;
      o[nt][2] *= c1; o[nt][3] *= c1;
    }
    uint32_t pf[4][4];
#pragma unroll
    for (int kc2 = 0; kc2 < 4; kc2++) {
      int nt0 = kc2 * 2, nt1 = kc2 * 2 + 1;
      float p00 = __expf(s[nt0][0] - m0), p01 = __expf(s[nt0][1] - m0);
      float p02 = __expf(s[nt0][2] - m1), p03 = __expf(s[nt0][3] - m1);
      float p10 = __expf(s[nt1][0] - m0), p11 = __expf(s[nt1][1] - m0);
      float p12 = __expf(s[nt1][2] - m1), p13 = __expf(s[nt1][3] - m1);
      l0 += p00 + p01 + p10 + p11;
      l1 += p02 + p03 + p12 + p13;
      pf[kc2][0] = f2h2u(p00, p01);
      pf[kc2][1] = f2h2u(p02, p03);
      pf[kc2][2] = f2h2u(p10, p11);
      pf[kc2][3] = f2h2u(p12, p13);
    }
    // ---- O += P V ----
    uint32_t vBase = sV + st * KVSTG;
#pragma unroll
    for (int kc2 = 0; kc2 < 4; kc2++) {
      uint32_t va = vBase + (uint32_t)(((kc2 * 16 + l15) * ATP + lhi * 8) * 2);
#pragma unroll
      for (int nh = 0; nh < 4; nh++) {   // each covers 2 hd n-tiles
        uint32_t vb[4];
        ldsm4t(vb, va + nh * 32);
        mma_f16(o[nh*2],   pf[kc2][0], pf[kc2][1], pf[kc2][2], pf[kc2][3], vb[0], vb[1]);
        mma_f16(o[nh*2+1], pf[kc2][0], pf[kc2][1], pf[kc2][2], pf[kc2][3], vb[2], vb[3]);
      }
    }
    __syncthreads();
  }

  // quad-reduce l (m already shared across quad)
  l0 += __shfl_xor_sync(0xffffffffu, l0, 1);
  l0 += __shfl_xor_sync(0xffffffffu, l0, 2);
  l1 += __shfl_xor_sync(0xffffffffu, l1, 1);
  l1 += __shfl_xor_sync(0xffffffffu, l1, 2);
  float inv0 = 1.f / l0, inv1 = 1.f / l1;

  int r0 = qBlock + qWarp + mq;
  __half* out0 = h_attn + (size_t)(b*SS + r0) * DD + h * HDD;
  __half* out1 = out0 + (size_t)8 * DD;
#pragma unroll
  for (int nt = 0; nt < 8; nt++) {
    int n = nt * 8 + 2 * kq;
    *(__half2*)(out0 + n) = __floats2half2_rn(o[nt][0] * inv0, o[nt][1] * inv0);
    *(__half2*)(out1 + n) = __floats2half2_rn(o[nt][2] * inv1, o[nt][3] * inv1);
  }
}

// ---------------- MoE routing ------------------------------------------------
__global__ void zero_kernel() { if (threadIdx.x < EE) g_cnt[threadIdx.x] = 0; }

__global__ __launch_bounds__(256) void gate_kernel(const float* __restrict__ gw) {
  int warp = (blockIdx.x * 256 + threadIdx.x) >> 5;
  int lane = threadIdx.x & 31;
  if (warp >= TT) return;
  const __half* x = h_h2 + (size_t)warp * DD;
  float acc[EE] = {};
  for (int k = lane; k < DD; k += 32) {
    float xv = __half2float(x[k]);
    const float* g = gw + (size_t)k * EE;
#pragma unroll
    for (int e = 0; e < EE; e++) acc[e] += xv * g[e];
  }
#pragma unroll
  for (int e = 0; e < EE; e++)
#pragma unroll
    for (int o = 16; o; o >>= 1) acc[e] += __shfl_xor_sync(0xffffffffu, acc[e], o);
  if (lane == 0) {
    float mx = acc[0];
#pragma unroll
    for (int e = 1; e < EE; e++) mx = fmaxf(mx, acc[e]);
    float p[EE];
#pragma unroll
    for (int e = 0; e < EE; e++) p[e] = __expf(acc[e] - mx);
    int i0 = 0;
#pragma unroll
    for (int e = 1; e < EE; e++) if (p[e] > p[i0]) i0 = e;
    int i1 = (i0 == 0) ? 1 : 0;
#pragma unroll
    for (int e = 0; e < EE; e++) if (e != i0 && p[e] > p[i1]) i1 = e;
    float w0 = p[i0], w1 = p[i1];
    float inv = 1.f / (w0 + w1);
    w0 *= inv; w1 *= inv;
    g_te[warp*2] = i0; g_te[warp*2+1] = i1;
    g_tw[warp*2] = w0; g_tw[warp*2+1] = w1;
    atomicAdd(&g_cnt[i0], 1);
    atomicAdd(&g_cnt[i1], 1);
  }
}

__global__ void scan_kernel() {
  if (threadIdx.x == 0) {
    int o = 0;
    for (int e = 0; e < EE; e++) { g_off[e] = o; o += g_cnt[e]; g_cur[e] = 0; }
    g_off[EE] = o;
  }
}

__global__ __launch_bounds__(256) void scatter_kernel() {
  int t = blockIdx.x * 256 + threadIdx.x;
  if (t >= TT) return;
#pragma unroll
  for (int k = 0; k < 2; k++) {
    int e = g_te[t*2+k];
    int pos = atomicAdd(&g_cur[e], 1);
    int slot = g_off[e] + pos;
    g_tok[slot] = t;
    g_slotw[slot] = g_tw[t*2+k];
    g_tokslot[t*2+k] = slot;
  }
}

// ---------------- activation --------------------------------------------------
__global__ __launch_bounds__(256) void act_kernel() {
  size_t i = ((size_t)blockIdx.x * 256 + threadIdx.x) * 8;
  __half2* a = (__half2*)(h_act + i);
  const __half2* h = (const __half2*)(h_h3v + i);
#pragma unroll
  for (int j = 0; j < 4; j++) {
    float2 h1 = __half22float2(a[j]);
    float2 h3 = __half22float2(h[j]);
    h1.x = h1.x / (1.f + __expf(-h1.x)) * h3.x;
    h1.y = h1.y / (1.f + __expf(-h1.y)) * h3.y;
    a[j] = __floats2half2_rn(h1.x, h1.y);
  }
}

// ---------------- combine ----------------------------------------------------
__global__ __launch_bounds__(256) void combine_kernel(float* __restrict__ outh) {
  int t = blockIdx.x;
  int s0 = g_tokslot[t*2], s1 = g_tokslot[t*2+1];
  int i = threadIdx.x * 4;
  float4 h  = *(float4*)(outh + (size_t)t * DD + i);
  float4 p0 = *(const float4*)(g_part + (size_t)s0 * DD + i);
  float4 p1 = *(const float4*)(g_part + (size_t)s1 * DD + i);
  h.x += p0.x + p1.x; h.y += p0.y + p1.y; h.z += p0.z + p1.z; h.w += p0.w + p1.w;
  *(float4*)(outh + (size_t)t * DD + i) = h;
  __half2* o = (__half2*)(h_outh + (size_t)t * DD + i);
  o[0] = __floats2half2_rn(h.x, h.y);
  o[1] = __floats2half2_rn(h.z, h.w);
}

// ---------------- launcher ---------------------------------------------------
static inline int cvgrid(int n) { return (n / 4 + 255) / 256; }

extern "C" void kernel_launch(void* const* d_in, const int* in_sizes, int n_in,
                              void* d_out, int out_size) {
  const float* hidden = (const float*)d_in[0];
  const float* prev   = (const float*)d_in[2];
  const float* wq     = (const float*)d_in[3];
  const float* wk     = (const float*)d_in[4];
  const float* wv     = (const float*)d_in[5];
  const float* wo     = (const float*)d_in[6];
  const float* mixw   = (const float*)d_in[7];
  const float* mixb   = (const float*)d_in[8];
  const float* gatew  = (const float*)d_in[9];
  const float* w1     = (const float*)d_in[10];
  const float* w2     = (const float*)d_in[11];
  const float* w3     = (const float*)d_in[12];
  const float* ln1    = (const float*)d_in[13];
  const float* ln2    = (const float*)d_in[14];
  const float* compw  = (const float*)d_in[15];
  const float* compb  = (const float*)d_in[16];

  float* out_h     = (float*)d_out;
  float* out_mixed = out_h + (size_t)TT * DD;
  float* out_comp  = out_mixed + (size_t)TT * DD;

  void *pwq,*pwk,*pwv,*pwo,*pmix,*pw1,*pw2,*pw3,*pcw,*pprev;
  void *pX,*pQh,*pKh,*pVh,*pAT,*pAO,*pH2,*pACT,*pH3,*pOH,*pPart;
  cudaGetSymbolAddress(&pwq, h_wq);   cudaGetSymbolAddress(&pwk, h_wk);
  cudaGetSymbolAddress(&pwv, h_wv);   cudaGetSymbolAddress(&pwo, h_wo);
  cudaGetSymbolAddress(&pmix, h_mixw);cudaGetSymbolAddress(&pw1, h_w1);
  cudaGetSymbolAddress(&pw2, h_w2);   cudaGetSymbolAddress(&pw3, h_w3);
  cudaGetSymbolAddress(&pcw, h_compw);cudaGetSymbolAddress(&pprev, h_prev);
  cudaGetSymbolAddress(&pX, h_X);     cudaGetSymbolAddress(&pQh, h_Qh);
  cudaGetSymbolAddress(&pKh, h_Kh);   cudaGetSymbolAddress(&pVh, h_Vh);
  cudaGetSymbolAddress(&pAT, h_attn);
  cudaGetSymbolAddress(&pAO, h_AO);   cudaGetSymbolAddress(&pH2, h_h2);
  cudaGetSymbolAddress(&pACT, h_act); cudaGetSymbolAddress(&pH3, h_h3v);
  cudaGetSymbolAddress(&pOH, h_outh); cudaGetSymbolAddress(&pPart, g_part);
  __half *HWQ=(__half*)pwq, *HWK=(__half*)pwk, *HWV=(__half*)pwv, *HWO=(__half*)pwo;
  __half *HMIX=(__half*)pmix, *HW1=(__half*)pw1, *HW2=(__half*)pw2, *HW3=(__half*)pw3;
  __half *HCW=(__half*)pcw, *HPREV=(__half*)pprev;
  __half *HX=(__half*)pX, *HQ=(__half*)pQh, *HK=(__half*)pKh, *HV=(__half*)pVh;
  __half *HAT=(__half*)pAT, *HAO=(__half*)pAO, *HH2=(__half*)pH2;
  __half *HACT=(__half*)pACT, *HH3=(__half*)pH3, *HOH=(__half*)pOH;
  float *PART=(float*)pPart;

  cudaFuncSetAttribute(gemm_h<0>, cudaFuncAttributeMaxDynamicSharedMemorySize, GSMEM);
  cudaFuncSetAttribute(gemm_h<1>, cudaFuncAttributeMaxDynamicSharedMemorySize, GSMEM);
  cudaFuncSetAttribute(gemm_h<2>, cudaFuncAttributeMaxDynamicSharedMemorySize, GSMEM);
  cudaFuncSetAttribute(gemm_h<3>, cudaFuncAttributeMaxDynamicSharedMemorySize, GSMEM);
  cudaFuncSetAttribute(gemm_h<4>, cudaFuncAttributeMaxDynamicSharedMemorySize, GSMEM);

  // ---- one-time fp32 -> fp16 conversions ----
  f2h_kernel<<<cvgrid(DD*DD), 256>>>(wq, HWQ, DD*DD);
  f2h_kernel<<<cvgrid(DD*256), 256>>>(wk, HWK, DD*256);
  f2h_kernel<<<cvgrid(DD*256), 256>>>(wv, HWV, DD*256);
  f2h_kernel<<<cvgrid(DD*DD), 256>>>(wo, HWO, DD*DD);
  f2h_kernel<<<cvgrid(2*DD*DD), 256>>>(mixw, HMIX, 2*DD*DD);
  f2h_kernel<<<cvgrid(EE*DD*FFF), 256>>>(w1, HW1, EE*DD*FFF);
  f2h_kernel<<<cvgrid(EE*FFF*DD), 256>>>(w2, HW2, EE*FFF*DD);
  f2h_kernel<<<cvgrid(EE*DD*FFF), 256>>>(w3, HW3, EE*DD*FFF);
  f2h_kernel<<<cvgrid(DD*CCOMP), 256>>>(compw, HCW, DD*CCOMP);
  f2h_kernel<<<cvgrid(TT*DD), 256>>>(prev, HPREV, TT*DD);

  // ---- pipeline ----
  rmsnorm_kernel<<<TT, 256>>>(hidden, ln1, HX);
  gemm_h<4><<<dim3(12, TT/128), 256, GSMEM>>>(
      HX, nullptr, HWQ, HWK, HWV, nullptr, nullptr,
      (float*)HQ, (float*)HK, (float*)HV, nullptr, DD, DD);
  attn_tc_kernel<<<dim3(SS/64, HH, BB), 128>>>();
  gemm_h<0><<<dim3(DD/128, TT/128), 256, GSMEM>>>(
      HAT, nullptr, HWO, nullptr, nullptr, nullptr, nullptr,
      nullptr, nullptr, nullptr, HAO, DD, DD);
  gemm_h<1><<<dim3(DD/128, TT/128), 256, GSMEM>>>(
      HAO, HPREV, HMIX, nullptr, nullptr, mixb, hidden,
      out_mixed, out_h, nullptr, nullptr, 2*DD, DD);
  rmsnorm_kernel<<<TT, 256>>>(out_h, ln2, HH2);
  zero_kernel<<<1, 32>>>();
  gate_kernel<<<TT/8, 256>>>(gatew);
  scan_kernel<<<1, 32>>>();
  scatter_kernel<<<TT/256, 256>>>();
  gemm_h<2><<<dim3(FFF/128, TT/128, EE), 256, GSMEM>>>(
      HH2, nullptr, HW1, nullptr, nullptr, nullptr, nullptr,
      nullptr, nullptr, nullptr, HACT, DD, FFF);
  gemm_h<2><<<dim3(FFF/128, TT/128, EE), 256, GSMEM>>>(
      HH2, nullptr, HW3, nullptr, nullptr, nullptr, nullptr,
      nullptr, nullptr, nullptr, HH3, DD, FFF);
  act_kernel<<<(int)(((size_t)NSLOT*FFF)/(256*8)), 256>>>();
  gemm_h<3><<<dim3(DD/128, TT/128, EE), 256, GSMEM>>>(
      HACT, nullptr, HW2, nullptr, nullptr, nullptr, nullptr,
      PART, nullptr, nullptr, nullptr, FFF, DD);
  combine_kernel<<<TT, 256>>>(out_h);
  gemm_h<0><<<dim3(CCOMP/128, TT/128), 256, GSMEM>>>(
      HOH, nullptr, HCW, nullptr, nullptr, compb, nullptr,
      out_comp, nullptr, nullptr, nullptr, DD, CCOMP);
}